// round 13
// baseline (speedup 1.0000x reference)
#include <cuda_runtime.h>
#include <cuda_fp16.h>
#include <math.h>
#include <stdint.h>

#define Bn   4
#define CINn 256
#define Fn   128
#define Nn   4096
#define EPSc 1e-5f
#define NSPLIT 2
#define KEYS_PER_SPLIT (Nn / NSPLIT)

// ---------------- scratch (device globals: no allocation allowed) ----------
__device__ __half d_x16[(size_t)Bn * Nn * CINn];  // x transposed [b][n][c] fp16
__device__ __half d_w16[4 * 32768];               // Wg,Wt,Wp [128][256]; Wz [256][128]
__device__ __half d_t16[(size_t)Bn * Nn * Fn];    // theta, [b][n][f]
__device__ __half d_p16[(size_t)Bn * Nn * Fn];    // phi,   [b][n][f]
__device__ __half d_g16[(size_t)Bn * Fn * Nn];    // g,     [b][f][n]
__device__ __half d_y16[(size_t)Bn * Nn * Fn];    // y,     [b][n][f]
__device__ float  d_po[(size_t)NSPLIT * Bn * Nn * Fn];  // split partial O (unnorm)
__device__ float  d_pm[NSPLIT * Bn * Nn];               // split partial max
__device__ float  d_pl[NSPLIT * Bn * Nn];               // split partial sum
__device__ float  d_z[(size_t)Bn * CINn * Nn];    // pre-LN output [b][c][n]
__device__ float  d_part[2 * Bn * 128];           // per-tile (sum,sumsq) partials
__device__ float  d_stats[2 * Bn];                // per-batch (mu, rsig)

// ---------------- helpers ---------------------------------------------------
__device__ __forceinline__ void mma16(float c[4],
        uint32_t a0, uint32_t a1, uint32_t a2, uint32_t a3,
        uint32_t b0, uint32_t b1) {
    asm volatile(
        "mma.sync.aligned.m16n8k16.row.col.f32.f16.f16.f32 "
        "{%0,%1,%2,%3}, {%4,%5,%6,%7}, {%8,%9}, {%0,%1,%2,%3};\n"
        : "+f"(c[0]), "+f"(c[1]), "+f"(c[2]), "+f"(c[3])
        : "r"(a0), "r"(a1), "r"(a2), "r"(a3), "r"(b0), "r"(b1));
}
__device__ __forceinline__ uint32_t ldu32(const __half* p) {
    return *(const uint32_t*)p;
}
__device__ __forceinline__ uint32_t packh2(float a, float b) {
    __half2 h = __floats2half2_rn(a, b);
    return *(uint32_t*)&h;
}
__device__ __forceinline__ void cpa16(uint32_t dst, const void* src) {
    asm volatile("cp.async.cg.shared.global [%0], [%1], 16;" :: "r"(dst), "l"(src));
}
#define CP_COMMIT() asm volatile("cp.async.commit_group;")
#define CP_WAIT1()  asm volatile("cp.async.wait_group 1;")
__device__ __forceinline__ uint32_t s2u(const void* p) {
    return (uint32_t)__cvta_generic_to_shared(p);
}
__device__ __forceinline__ void ldsm4(uint32_t& r0, uint32_t& r1,
                                      uint32_t& r2, uint32_t& r3,
                                      const __half* addr) {
    asm volatile("ldmatrix.sync.aligned.m8n8.x4.shared.b16 {%0,%1,%2,%3}, [%4];"
        : "=r"(r0), "=r"(r1), "=r"(r2), "=r"(r3) : "r"(s2u(addr)));
}

// ============================================================================
// kernel 0a: convert the four weight matrices to fp16 (once per launch)
// ============================================================================
__global__ __launch_bounds__(256) void prep_w(
    const float* __restrict__ Wg, const float* __restrict__ Wt,
    const float* __restrict__ Wp, const float* __restrict__ Wz)
{
    const float* srcs[4] = {Wg, Wt, Wp, Wz};
    int stride = gridDim.x * blockDim.x;
    for (int i = blockIdx.x * blockDim.x + threadIdx.x; i < 4 * 8192; i += stride) {
        int w = i >> 13;
        int e = i & 8191;
        float4 v = ((const float4*)srcs[w])[e];
        *(__half2*)&d_w16[(size_t)w * 32768 + e * 4]     = __floats2half2_rn(v.x, v.y);
        *(__half2*)&d_w16[(size_t)w * 32768 + e * 4 + 2] = __floats2half2_rn(v.z, v.w);
    }
}

// ============================================================================
// kernel 0b: transpose x [b][c][n] fp32 -> d_x16 [b][n][c] fp16
// ============================================================================
__global__ __launch_bounds__(256) void xpose(const float* __restrict__ x)
{
    __shared__ float t[64][33];
    int b  = blockIdx.z;
    int c0 = blockIdx.y * 64;
    int n0 = blockIdx.x * 32;
    const float* X = x + ((size_t)b * CINn + c0) * Nn;
    int tid = threadIdx.x;
    int tn = tid & 31, tc = tid >> 5;

    #pragma unroll
    for (int cc = tc; cc < 64; cc += 8)
        t[cc][tn] = X[(size_t)cc * Nn + n0 + tn];
    __syncthreads();

    int lane = tid & 31, warp = tid >> 5;
    __half* out = d_x16 + ((size_t)b * Nn + n0) * CINn + c0;
    #pragma unroll
    for (int nn = warp; nn < 32; nn += 8) {
        float v0 = t[2 * lane][nn], v1 = t[2 * lane + 1][nn];
        *(__half2*)&out[(size_t)nn * CINn + 2 * lane] = __floats2half2_rn(v0, v1);
    }
}

// ============================================================================
// kernel 1: the three 1x1-conv GEMMs on fp16 mma, K=256 fully resident
// ============================================================================
#define PW_PITCH 264
#define PROJ_SMEM ((128 + 64) * PW_PITCH * 2)

__global__ __launch_bounds__(256) void proj_mma(
    const float* __restrict__ bg, const float* __restrict__ bt,
    const float* __restrict__ bp)
{
    extern __shared__ char psm[];
    __half* Ws = (__half*)psm;                        // [128][264]
    __half* Xs = (__half*)(psm + 128 * PW_PITCH * 2); // [64][264]

    int pb   = blockIdx.y;
    int proj = pb % 3;
    int b    = pb / 3;
    const __half* Wm = d_w16 + (size_t)proj * 32768;
    const float* bias = (proj == 0) ? bg : (proj == 1 ? bt : bp);

    const __half* X16 = d_x16 + (size_t)b * Nn * CINn;
    int n0 = blockIdx.x * 64;

    int tid = threadIdx.x;
    int lane = tid & 31, warp = tid >> 5;
    int r = lane >> 2, cl = lane & 3;
    int qrow = warp * 16 + r;

    #pragma unroll
    for (int e = tid; e < 128 * 32; e += 256) {
        int m = e >> 5, c8 = (e & 31) * 8;
        *(uint4*)&Ws[m * PW_PITCH + c8] = *(const uint4*)&Wm[(size_t)m * 256 + c8];
    }
    #pragma unroll
    for (int e = tid; e < 64 * 32; e += 256) {
        int n = e >> 5, c8 = (e & 31) * 8;
        *(uint4*)&Xs[n * PW_PITCH + c8] =
            *(const uint4*)&X16[(size_t)(n0 + n) * CINn + c8];
    }
    __syncthreads();

    float acc[8][4];
    #pragma unroll
    for (int i = 0; i < 8; i++)
        #pragma unroll
        for (int j = 0; j < 4; j++) acc[i][j] = 0.f;

    #pragma unroll
    for (int kk = 0; kk < CINn; kk += 16) {
        uint32_t a0 = ldu32(&Ws[qrow       * PW_PITCH + kk + 2 * cl    ]);
        uint32_t a1 = ldu32(&Ws[(qrow + 8) * PW_PITCH + kk + 2 * cl    ]);
        uint32_t a2 = ldu32(&Ws[qrow       * PW_PITCH + kk + 2 * cl + 8]);
        uint32_t a3 = ldu32(&Ws[(qrow + 8) * PW_PITCH + kk + 2 * cl + 8]);
        #pragma unroll
        for (int nt = 0; nt < 8; nt++) {
            int nc = nt * 8 + r;
            uint32_t b0 = ldu32(&Xs[nc * PW_PITCH + kk + 2 * cl    ]);
            uint32_t b1 = ldu32(&Xs[nc * PW_PITCH + kk + 2 * cl + 8]);
            mma16(acc[nt], a0, a1, a2, a3, b0, b1);
        }
    }

    float bi0 = bias[qrow], bi1 = bias[qrow + 8];
    if (proj == 0) {
        __half* out = d_g16 + (size_t)b * Fn * Nn;
        #pragma unroll
        for (int nt = 0; nt < 8; nt++) {
            int nc = n0 + nt * 8 + 2 * cl;
            *(__half2*)&out[(size_t)qrow * Nn + nc] =
                __floats2half2_rn(acc[nt][0] + bi0, acc[nt][1] + bi0);
            *(__half2*)&out[(size_t)(qrow + 8) * Nn + nc] =
                __floats2half2_rn(acc[nt][2] + bi1, acc[nt][3] + bi1);
        }
    } else {
        __half* out = (proj == 1 ? d_t16 : d_p16) + (size_t)b * Nn * Fn;
        #pragma unroll
        for (int nt = 0; nt < 8; nt++) {
            int nc = n0 + nt * 8 + 2 * cl;
            out[(size_t)nc       * Fn + qrow    ] = __float2half_rn(acc[nt][0] + bi0);
            out[(size_t)(nc + 1) * Fn + qrow    ] = __float2half_rn(acc[nt][1] + bi0);
            out[(size_t)nc       * Fn + qrow + 8] = __float2half_rn(acc[nt][2] + bi1);
            out[(size_t)(nc + 1) * Fn + qrow + 8] = __float2half_rn(acc[nt][3] + bi1);
        }
    }
}

// ============================================================================
// kernel 2: flash attention, split-K(2), 4-warp CTAs (q-block 64), 2-stage
//   cp.async pipeline (72KB smem) -> 3 CTAs/SM (12 warps) under 170 regs.
//   theta + P in registers; B fragments via ldmatrix.x4; partials (O,m,l)
//   to gmem, merged by ymerge.
// ============================================================================
#define PH_HALVES (64 * 136)           // phi stage  [m][f], pitch 136
#define GS_HALVES (128 * 72)           // g   stage  [f][m], pitch 72
#define STAGE_HALVES (PH_HALVES + GS_HALVES)
#define ATTN_SMEM (2 * STAGE_HALVES * 2)

__global__ __launch_bounds__(128, 3) void attn_kernel()
{
    extern __shared__ __half sh[];

    int b  = blockIdx.y;
    int q0 = blockIdx.x * 64;
    int sp = blockIdx.z;
    int k0 = sp * KEYS_PER_SPLIT;
    const __half* t16 = d_t16 + (size_t)b * Nn * Fn;
    const __half* p16 = d_p16 + (size_t)b * Nn * Fn;
    const __half* g16 = d_g16 + (size_t)b * Fn * Nn;

    int tid  = threadIdx.x;
    int lane = tid & 31, warp = tid >> 5;
    int r = lane >> 2, cl = lane & 3;
    int qrow = warp * 16 + r;
    int lg = lane >> 3;
    int li = lane & 7;
    int rlo = (lg >> 1) * 8 + li;
    int koff = (lg & 1) * 8;

    // ---- theta fragments -> registers (one-time gmem read) ----
    uint32_t th[8][4];
    {
        const __half* t0 = &t16[(size_t)(q0 + qrow) * Fn];
        const __half* t1 = &t16[(size_t)(q0 + qrow + 8) * Fn];
        #pragma unroll
        for (int kk = 0; kk < 8; kk++) {
            th[kk][0] = ldu32(&t0[kk * 16 + 2 * cl]);
            th[kk][1] = ldu32(&t1[kk * 16 + 2 * cl]);
            th[kk][2] = ldu32(&t0[kk * 16 + 2 * cl + 8]);
            th[kk][3] = ldu32(&t1[kk * 16 + 2 * cl + 8]);
        }
    }

    float oc[16][4];
    #pragma unroll
    for (int i = 0; i < 16; i++)
        #pragma unroll
        for (int j = 0; j < 4; j++) oc[i][j] = 0.f;

    float m0_ = -3.0e38f, m1_ = -3.0e38f;
    float l0_ = 0.f,      l1_ = 0.f;

    // ---- cp.async chunk issue (128 threads) ----
    auto issue = [&](int mb, int s) {
        __half* ph = sh + s * STAGE_HALVES;
        __half* gs = ph + PH_HALVES;
        #pragma unroll
        for (int i = 0; i < 8; i++) {
            int e = tid + i * 128;
            int m = e >> 4, c8 = (e & 15) * 8;
            cpa16(s2u(&ph[m * 136 + c8]), &p16[(size_t)(mb + m) * Fn + c8]);
        }
        #pragma unroll
        for (int i = 0; i < 8; i++) {
            int e = tid + i * 128;
            int f = e >> 3, c8 = (e & 7) * 8;
            cpa16(s2u(&gs[f * 72 + c8]), &g16[(size_t)f * Nn + mb + c8]);
        }
    };

    const int NCH = KEYS_PER_SPLIT / 64;     // 32 chunks
    issue(k0, 0);      CP_COMMIT();
    issue(k0 + 64, 1); CP_COMMIT();

    for (int ic = 0; ic < NCH; ic++) {
        CP_WAIT1();
        __syncthreads();

        const __half* ph = sh + (ic & 1) * STAGE_HALVES;
        const __half* gs = ph + PH_HALVES;

        // ---- S = theta phi^T : 16q x 64m (ldsm4 interleaved with mma) ----
        float sc[8][4];
        #pragma unroll
        for (int i = 0; i < 8; i++)
            #pragma unroll
            for (int j = 0; j < 4; j++) sc[i][j] = 0.f;

        #pragma unroll
        for (int kk = 0; kk < 8; kk++) {
            #pragma unroll
            for (int p2 = 0; p2 < 4; p2++) {
                uint32_t f0, f1, f2, f3;
                ldsm4(f0, f1, f2, f3, &ph[(p2 * 16 + rlo) * 136 + kk * 16 + koff]);
                mma16(sc[p2 * 2],     th[kk][0], th[kk][1], th[kk][2], th[kk][3], f0, f1);
                mma16(sc[p2 * 2 + 1], th[kk][0], th[kk][1], th[kk][2], th[kk][3], f2, f3);
            }
        }

        // ---- online softmax (warp-local, all in registers) ----
        float mx0 = -3.0e38f, mx1 = -3.0e38f;
        #pragma unroll
        for (int nt = 0; nt < 8; nt++) {
            mx0 = fmaxf(mx0, fmaxf(sc[nt][0], sc[nt][1]));
            mx1 = fmaxf(mx1, fmaxf(sc[nt][2], sc[nt][3]));
        }
        #pragma unroll
        for (int o = 1; o < 4; o <<= 1) {
            mx0 = fmaxf(mx0, __shfl_xor_sync(0xffffffffu, mx0, o));
            mx1 = fmaxf(mx1, __shfl_xor_sync(0xffffffffu, mx1, o));
        }
        float nm0 = fmaxf(m0_, mx0), nm1 = fmaxf(m1_, mx1);
        float al0 = __expf(m0_ - nm0), al1 = __expf(m1_ - nm1);
        m0_ = nm0; m1_ = nm1;

        uint32_t pp[8], pq[8];
        float rs0 = 0.f, rs1 = 0.f;
        #pragma unroll
        for (int nt = 0; nt < 8; nt++) {
            float p0 = __expf(sc[nt][0] - nm0);
            float p1 = __expf(sc[nt][1] - nm0);
            float p2 = __expf(sc[nt][2] - nm1);
            float p3 = __expf(sc[nt][3] - nm1);
            rs0 += p0 + p1; rs1 += p2 + p3;
            pp[nt] = packh2(p0, p1);
            pq[nt] = packh2(p2, p3);
        }
        #pragma unroll
        for (int o = 1; o < 4; o <<= 1) {
            rs0 += __shfl_xor_sync(0xffffffffu, rs0, o);
            rs1 += __shfl_xor_sync(0xffffffffu, rs1, o);
        }
        l0_ = l0_ * al0 + rs0;
        l1_ = l1_ * al1 + rs1;

        #pragma unroll
        for (int ft = 0; ft < 16; ft++) {
            oc[ft][0] *= al0; oc[ft][1] *= al0;
            oc[ft][2] *= al1; oc[ft][3] *= al1;
        }

        // ---- O += P G^T : P from registers, ldsm4 interleaved ----
        #pragma unroll
        for (int j = 0; j < 4; j++) {
            uint32_t a0 = pp[2 * j], a1 = pq[2 * j];
            uint32_t a2 = pp[2 * j + 1], a3 = pq[2 * j + 1];
            #pragma unroll
            for (int p2 = 0; p2 < 8; p2++) {
                uint32_t f0, f1, f2, f3;
                ldsm4(f0, f1, f2, f3, &gs[(p2 * 16 + rlo) * 72 + j * 16 + koff]);
                mma16(oc[p2 * 2],     a0, a1, a2, a3, f0, f1);
                mma16(oc[p2 * 2 + 1], a0, a1, a2, a3, f2, f3);
            }
        }

        __syncthreads();   // all warps done reading this stage
        if (ic + 2 < NCH) issue(k0 + (ic + 2) * 64, ic & 1);
        CP_COMMIT();
    }

    // ---- epilogue: write unnormalized partials (O, m, l) ----
    size_t rbase = ((size_t)sp * Bn + b) * Nn + q0;
    float* po = d_po + (rbase + qrow) * Fn;
    float* po8 = d_po + (rbase + qrow + 8) * Fn;
    #pragma unroll
    for (int ft = 0; ft < 16; ft++) {
        int fb = ft * 8 + 2 * cl;
        *(float2*)&po[fb]  = make_float2(oc[ft][0], oc[ft][1]);
        *(float2*)&po8[fb] = make_float2(oc[ft][2], oc[ft][3]);
    }
    if (cl == 0) {
        d_pm[rbase + qrow]     = m0_;
        d_pm[rbase + qrow + 8] = m1_;
        d_pl[rbase + qrow]     = l0_;
        d_pl[rbase + qrow + 8] = l1_;
    }
}

// ============================================================================
// kernel 2b: merge split-K partials -> y16 [b][n][f]
// ============================================================================
__global__ __launch_bounds__(256) void ymerge()
{
    int warp = threadIdx.x >> 5, lane = threadIdx.x & 31;
    int row = blockIdx.x * 8 + warp;          // 0 .. Bn*Nn-1
    const size_t SOFF = (size_t)Bn * Nn;

    float m0 = d_pm[row], m1 = d_pm[SOFF + row];
    float l0 = d_pl[row], l1 = d_pl[SOFF + row];
    float ms = fmaxf(m0, m1);
    float w0 = __expf(m0 - ms), w1 = __expf(m1 - ms);
    float inv = 1.0f / (l0 * w0 + l1 * w1);
    float c0 = w0 * inv, c1 = w1 * inv;

    const float* o0 = d_po + (size_t)row * Fn;
    const float* o1 = d_po + (SOFF + row) * Fn;
    __half* y = d_y16 + (size_t)row * Fn;
    int f = lane * 4;
    float4 a = *(const float4*)&o0[f];
    float4 c = *(const float4*)&o1[f];
    *(__half2*)&y[f]     = __floats2half2_rn(a.x * c0 + c.x * c1, a.y * c0 + c.y * c1);
    *(__half2*)&y[f + 2] = __floats2half2_rn(a.z * c0 + c.z * c1, a.w * c0 + c.w * c1);
}

// ============================================================================
// kernel 3: z = Wz @ y + bz on fp16 mma (single K pass), LN partials fused
// ============================================================================
#define ZW_PITCH 136
#define ZY_PITCH 136
#define ZG_SMEM (128 * ZW_PITCH * 2 + 64 * ZY_PITCH * 2)

__global__ __launch_bounds__(256) void zgemm_mma(const float* __restrict__ bz)
{
    extern __shared__ char zsm[];
    __half* Ws = (__half*)zsm;                        // [128][136]
    __half* Ys = (__half*)(zsm + 128 * ZW_PITCH * 2); // [64][136]

    int b  = blockIdx.z;
    int m0 = blockIdx.y * 128;
    int n0 = blockIdx.x * 64;
    const __half* W16z = d_w16 + (size_t)3 * 32768;   // [256][128]
    const __half* Y16 = d_y16 + (size_t)b * Nn * Fn;
    float* Z = d_z + (size_t)b * CINn * Nn;

    int tid = threadIdx.x;
    int lane = tid & 31, warp = tid >> 5;
    int r = lane >> 2, cl = lane & 3;
    int qrow = warp * 16 + r;

    #pragma unroll
    for (int e = tid; e < 128 * 16; e += 256) {
        int m = e >> 4, c8 = (e & 15) * 8;
        *(uint4*)&Ws[m * ZW_PITCH + c8] =
            *(const uint4*)&W16z[(size_t)(m0 + m) * Fn + c8];
    }
    #pragma unroll
    for (int e = tid; e < 64 * 16; e += 256) {
        int n = e >> 4, c8 = (e & 15) * 8;
        *(uint4*)&Ys[n * ZY_PITCH + c8] = *(const uint4*)&Y16[(size_t)(n0 + n) * Fn + c8];
    }
    __syncthreads();

    float acc[8][4];
    #pragma unroll
    for (int i = 0; i < 8; i++)
        #pragma unroll
        for (int j = 0; j < 4; j++) acc[i][j] = 0.f;

    #pragma unroll
    for (int kk = 0; kk < Fn; kk += 16) {
        uint32_t a0 = ldu32(&Ws[qrow       * ZW_PITCH + kk + 2 * cl    ]);
        uint32_t a1 = ldu32(&Ws[(qrow + 8) * ZW_PITCH + kk + 2 * cl    ]);
        uint32_t a2 = ldu32(&Ws[qrow       * ZW_PITCH + kk + 2 * cl + 8]);
        uint32_t a3 = ldu32(&Ws[(qrow + 8) * ZW_PITCH + kk + 2 * cl + 8]);
        #pragma unroll
        for (int nt = 0; nt < 8; nt++) {
            int nc = nt * 8 + r;
            uint32_t b0 = ldu32(&Ys[nc * ZY_PITCH + kk + 2 * cl    ]);
            uint32_t b1 = ldu32(&Ys[nc * ZY_PITCH + kk + 2 * cl + 8]);
            mma16(acc[nt], a0, a1, a2, a3, b0, b1);
        }
    }
    __syncthreads();

    float bi0 = bz[m0 + qrow], bi1 = bz[m0 + qrow + 8];
    float lsum = 0.f, lsq = 0.f;
    #pragma unroll
    for (int nt = 0; nt < 8; nt++) {
        int nc = n0 + nt * 8 + 2 * cl;
        float v0 = acc[nt][0] + bi0, v1 = acc[nt][1] + bi0;
        float v2 = acc[nt][2] + bi1, v3 = acc[nt][3] + bi1;
        *(float2*)&Z[(size_t)(m0 + qrow) * Nn + nc]     = make_float2(v0, v1);
        *(float2*)&Z[(size_t)(m0 + qrow + 8) * Nn + nc] = make_float2(v2, v3);
        lsum += v0 + v1 + v2 + v3;
        lsq  += v0 * v0 + v1 * v1 + v2 * v2 + v3 * v3;
    }

    float* rs = (float*)zsm;
    float* rq = rs + 256;
    rs[tid] = lsum; rq[tid] = lsq;
    __syncthreads();
    #pragma unroll
    for (int s = 128; s > 0; s >>= 1) {
        if (tid < s) { rs[tid] += rs[tid + s]; rq[tid] += rq[tid + s]; }
        __syncthreads();
    }
    if (tid == 0) {
        int idx = b * 128 + blockIdx.y * 64 + blockIdx.x;
        d_part[2 * idx]     = rs[0];
        d_part[2 * idx + 1] = rq[0];
    }
}

// ---------------- kernel 4: per-batch mean / rsig ---------------------------
__global__ __launch_bounds__(128) void stats_kernel()
{
    int b = blockIdx.x;
    int tid = threadIdx.x;
    __shared__ float rs[128], rq[128];
    int idx = b * 128 + tid;
    rs[tid] = d_part[2 * idx];
    rq[tid] = d_part[2 * idx + 1];
    __syncthreads();
    #pragma unroll
    for (int s = 64; s > 0; s >>= 1) {
        if (tid < s) { rs[tid] += rs[tid + s]; rq[tid] += rq[tid + s]; }
        __syncthreads();
    }
    if (tid == 0) {
        float inv = 1.0f / ((float)CINn * (float)Nn);
        float mu  = rs[0] * inv;
        float var = rq[0] * inv - mu * mu;
        d_stats[2 * b]     = mu;
        d_stats[2 * b + 1] = rsqrtf(var + EPSc);
    }
}

// ---------------- kernel 5: LN affine + residual ----------------------------
__global__ __launch_bounds__(256) void finalize_kernel(
    const float* __restrict__ x, const float* __restrict__ lw,
    const float* __restrict__ lb, float* __restrict__ out)
{
    const int per_b4 = CINn * Nn / 4;
    const int tot4   = Bn * per_b4;
    for (int i = blockIdx.x * blockDim.x + threadIdx.x; i < tot4;
         i += gridDim.x * blockDim.x) {
        int b = i / per_b4;
        int r = i - b * per_b4;
        float mu   = d_stats[2 * b];
        float rsig = d_stats[2 * b + 1];
        float4 z  = ((const float4*)d_z)[i];
        float4 xv = ((const float4*)x)[i];
        float4 w  = ((const float4*)lw)[r];
        float4 bb = ((const float4*)lb)[r];
        float4 o;
        o.x = (z.x - mu) * rsig * w.x + bb.x + xv.x;
        o.y = (z.y - mu) * rsig * w.y + bb.y + xv.y;
        o.z = (z.z - mu) * rsig * w.z + bb.z + xv.z;
        o.w = (z.w - mu) * rsig * w.w + bb.w + xv.w;
        ((float4*)out)[i] = o;
    }
}

// ---------------- launch -----------------------------------------------------
extern "C" void kernel_launch(void* const* d_in, const int* in_sizes, int n_in,
                              void* d_out, int out_size)
{
    const float* x   = (const float*)d_in[0];
    const float* Wg  = (const float*)d_in[1];
    const float* bg  = (const float*)d_in[2];
    const float* Wt  = (const float*)d_in[3];
    const float* bt  = (const float*)d_in[4];
    const float* Wp  = (const float*)d_in[5];
    const float* bp  = (const float*)d_in[6];
    const float* Wz  = (const float*)d_in[7];
    const float* bz  = (const float*)d_in[8];
    const float* lnw = (const float*)d_in[9];
    const float* lnb = (const float*)d_in[10];
    float* out = (float*)d_out;

    cudaFuncSetAttribute(attn_kernel, cudaFuncAttributeMaxDynamicSharedMemorySize,
                         ATTN_SMEM);
    cudaFuncSetAttribute(proj_mma, cudaFuncAttributeMaxDynamicSharedMemorySize,
                         PROJ_SMEM);
    cudaFuncSetAttribute(zgemm_mma, cudaFuncAttributeMaxDynamicSharedMemorySize,
                         ZG_SMEM);

    prep_w<<<128, 256>>>(Wg, Wt, Wp, Wz);
    xpose<<<dim3(128, 4, 4), 256>>>(x);
    proj_mma<<<dim3(64, 12), 256, PROJ_SMEM>>>(bg, bt, bp);
    attn_kernel<<<dim3(64, 4, NSPLIT), 128, ATTN_SMEM>>>();
    ymerge<<<Bn * Nn / 8, 256>>>();
    zgemm_mma<<<dim3(64, 2, 4), 256, ZG_SMEM>>>(bz);
    stats_kernel<<<4, 128>>>();
    finalize_kernel<<<4096, 256>>>(x, lnw, lnb, out);
}

// round 14
// speedup vs baseline: 1.2812x; 1.2812x over previous
#include <cuda_runtime.h>
#include <cuda_fp16.h>
#include <math.h>
#include <stdint.h>

#define Bn   4
#define CINn 256
#define Fn   128
#define Nn   4096
#define EPSc 1e-5f
#define LOG2E 1.4426950408889634f

// ---------------- scratch (device globals: no allocation allowed) ----------
__device__ __half d_x16[(size_t)Bn * Nn * CINn];  // x transposed [b][n][c] fp16
__device__ __half d_w16[4 * 32768];               // Wg,Wt,Wp [128][256]; Wz [256][128]
__device__ __half d_t16[(size_t)Bn * Nn * Fn];    // theta*log2e, [b][n][f]
__device__ __half d_p16[(size_t)Bn * Nn * Fn];    // phi,   [b][n][f]
__device__ __half d_g16[(size_t)Bn * Fn * Nn];    // g,     [b][f][n]
__device__ __half d_y16[(size_t)Bn * Nn * Fn];    // y,     [b][n][f]
__device__ float  d_z[(size_t)Bn * CINn * Nn];    // pre-LN output [b][c][n]
__device__ float  d_part[2 * Bn * 128];           // per-tile (sum,sumsq) partials
__device__ float  d_stats[2 * Bn];                // per-batch (mu, rsig)

// ---------------- helpers ---------------------------------------------------
__device__ __forceinline__ void mma16(float c[4],
        uint32_t a0, uint32_t a1, uint32_t a2, uint32_t a3,
        uint32_t b0, uint32_t b1) {
    asm volatile(
        "mma.sync.aligned.m16n8k16.row.col.f32.f16.f16.f32 "
        "{%0,%1,%2,%3}, {%4,%5,%6,%7}, {%8,%9}, {%0,%1,%2,%3};\n"
        : "+f"(c[0]), "+f"(c[1]), "+f"(c[2]), "+f"(c[3])
        : "r"(a0), "r"(a1), "r"(a2), "r"(a3), "r"(b0), "r"(b1));
}
__device__ __forceinline__ uint32_t ldu32(const __half* p) {
    return *(const uint32_t*)p;
}
__device__ __forceinline__ uint32_t packh2(float a, float b) {
    __half2 h = __floats2half2_rn(a, b);
    return *(uint32_t*)&h;
}
__device__ __forceinline__ void cpa16(uint32_t dst, const void* src) {
    asm volatile("cp.async.cg.shared.global [%0], [%1], 16;" :: "r"(dst), "l"(src));
}
#define CP_COMMIT() asm volatile("cp.async.commit_group;")
#define CP_WAIT1()  asm volatile("cp.async.wait_group 1;")
__device__ __forceinline__ uint32_t s2u(const void* p) {
    return (uint32_t)__cvta_generic_to_shared(p);
}
__device__ __forceinline__ void ldsm4(uint32_t& r0, uint32_t& r1,
                                      uint32_t& r2, uint32_t& r3,
                                      const __half* addr) {
    asm volatile("ldmatrix.sync.aligned.m8n8.x4.shared.b16 {%0,%1,%2,%3}, [%4];"
        : "=r"(r0), "=r"(r1), "=r"(r2), "=r"(r3) : "r"(s2u(addr)));
}

// ============================================================================
// kernel 0a: convert the four weight matrices to fp16 (once per launch)
// ============================================================================
__global__ __launch_bounds__(256) void prep_w(
    const float* __restrict__ Wg, const float* __restrict__ Wt,
    const float* __restrict__ Wp, const float* __restrict__ Wz)
{
    const float* srcs[4] = {Wg, Wt, Wp, Wz};
    int stride = gridDim.x * blockDim.x;
    for (int i = blockIdx.x * blockDim.x + threadIdx.x; i < 4 * 8192; i += stride) {
        int w = i >> 13;
        int e = i & 8191;
        float4 v = ((const float4*)srcs[w])[e];
        *(__half2*)&d_w16[(size_t)w * 32768 + e * 4]     = __floats2half2_rn(v.x, v.y);
        *(__half2*)&d_w16[(size_t)w * 32768 + e * 4 + 2] = __floats2half2_rn(v.z, v.w);
    }
}

// ============================================================================
// kernel 0b: transpose x [b][c][n] fp32 -> d_x16 [b][n][c] fp16
// ============================================================================
__global__ __launch_bounds__(256) void xpose(const float* __restrict__ x)
{
    __shared__ float t[64][33];
    int b  = blockIdx.z;
    int c0 = blockIdx.y * 64;
    int n0 = blockIdx.x * 32;
    const float* X = x + ((size_t)b * CINn + c0) * Nn;
    int tid = threadIdx.x;
    int tn = tid & 31, tc = tid >> 5;

    #pragma unroll
    for (int cc = tc; cc < 64; cc += 8)
        t[cc][tn] = X[(size_t)cc * Nn + n0 + tn];
    __syncthreads();

    int lane = tid & 31, warp = tid >> 5;
    __half* out = d_x16 + ((size_t)b * Nn + n0) * CINn + c0;
    #pragma unroll
    for (int nn = warp; nn < 32; nn += 8) {
        float v0 = t[2 * lane][nn], v1 = t[2 * lane + 1][nn];
        *(__half2*)&out[(size_t)nn * CINn + 2 * lane] = __floats2half2_rn(v0, v1);
    }
}

// ============================================================================
// kernel 1: the three 1x1-conv GEMMs on fp16 mma, K=256 fully resident
//   theta output pre-scaled by log2(e) for exp2-domain softmax.
// ============================================================================
#define PW_PITCH 264
#define PROJ_SMEM ((128 + 64) * PW_PITCH * 2)

__global__ __launch_bounds__(256) void proj_mma(
    const float* __restrict__ bg, const float* __restrict__ bt,
    const float* __restrict__ bp)
{
    extern __shared__ char psm[];
    __half* Ws = (__half*)psm;                        // [128][264]
    __half* Xs = (__half*)(psm + 128 * PW_PITCH * 2); // [64][264]

    int pb   = blockIdx.y;
    int proj = pb % 3;
    int b    = pb / 3;
    const __half* Wm = d_w16 + (size_t)proj * 32768;
    const float* bias = (proj == 0) ? bg : (proj == 1 ? bt : bp);

    const __half* X16 = d_x16 + (size_t)b * Nn * CINn;
    int n0 = blockIdx.x * 64;

    int tid = threadIdx.x;
    int lane = tid & 31, warp = tid >> 5;
    int r = lane >> 2, cl = lane & 3;
    int qrow = warp * 16 + r;

    #pragma unroll
    for (int e = tid; e < 128 * 32; e += 256) {
        int m = e >> 5, c8 = (e & 31) * 8;
        *(uint4*)&Ws[m * PW_PITCH + c8] = *(const uint4*)&Wm[(size_t)m * 256 + c8];
    }
    #pragma unroll
    for (int e = tid; e < 64 * 32; e += 256) {
        int n = e >> 5, c8 = (e & 31) * 8;
        *(uint4*)&Xs[n * PW_PITCH + c8] =
            *(const uint4*)&X16[(size_t)(n0 + n) * CINn + c8];
    }
    __syncthreads();

    float acc[8][4];
    #pragma unroll
    for (int i = 0; i < 8; i++)
        #pragma unroll
        for (int j = 0; j < 4; j++) acc[i][j] = 0.f;

    #pragma unroll
    for (int kk = 0; kk < CINn; kk += 16) {
        uint32_t a0 = ldu32(&Ws[qrow       * PW_PITCH + kk + 2 * cl    ]);
        uint32_t a1 = ldu32(&Ws[(qrow + 8) * PW_PITCH + kk + 2 * cl    ]);
        uint32_t a2 = ldu32(&Ws[qrow       * PW_PITCH + kk + 2 * cl + 8]);
        uint32_t a3 = ldu32(&Ws[(qrow + 8) * PW_PITCH + kk + 2 * cl + 8]);
        #pragma unroll
        for (int nt = 0; nt < 8; nt++) {
            int nc = nt * 8 + r;
            uint32_t b0 = ldu32(&Xs[nc * PW_PITCH + kk + 2 * cl    ]);
            uint32_t b1 = ldu32(&Xs[nc * PW_PITCH + kk + 2 * cl + 8]);
            mma16(acc[nt], a0, a1, a2, a3, b0, b1);
        }
    }

    float bi0 = bias[qrow], bi1 = bias[qrow + 8];
    if (proj == 0) {
        __half* out = d_g16 + (size_t)b * Fn * Nn;
        #pragma unroll
        for (int nt = 0; nt < 8; nt++) {
            int nc = n0 + nt * 8 + 2 * cl;
            *(__half2*)&out[(size_t)qrow * Nn + nc] =
                __floats2half2_rn(acc[nt][0] + bi0, acc[nt][1] + bi0);
            *(__half2*)&out[(size_t)(qrow + 8) * Nn + nc] =
                __floats2half2_rn(acc[nt][2] + bi1, acc[nt][3] + bi1);
        }
    } else {
        __half* out = (proj == 1 ? d_t16 : d_p16) + (size_t)b * Nn * Fn;
        float sc = (proj == 1) ? LOG2E : 1.0f;
        #pragma unroll
        for (int nt = 0; nt < 8; nt++) {
            int nc = n0 + nt * 8 + 2 * cl;
            out[(size_t)nc       * Fn + qrow    ] = __float2half_rn((acc[nt][0] + bi0) * sc);
            out[(size_t)(nc + 1) * Fn + qrow    ] = __float2half_rn((acc[nt][1] + bi0) * sc);
            out[(size_t)nc       * Fn + qrow + 8] = __float2half_rn((acc[nt][2] + bi1) * sc);
            out[(size_t)(nc + 1) * Fn + qrow + 8] = __float2half_rn((acc[nt][3] + bi1) * sc);
        }
    }
}

// ============================================================================
// kernel 2: fused flash attention, fp16 mma, 128-key stages, 3-stage cp.async
//   (209 KB smem), theta + P in registers, B frags via ldmatrix.x4,
//   ONE barrier per 128 keys. Softmax in exp2 domain (theta pre-scaled).
// ============================================================================
#define PH_HALVES (128 * 136)          // phi stage  [m][f],   m-chunk 128
#define GS_HALVES (128 * 136)          // g   stage  [f][m],   m-chunk 128
#define STAGE_HALVES (PH_HALVES + GS_HALVES)
#define ATTN_SMEM (3 * STAGE_HALVES * 2)

__global__ __launch_bounds__(256, 1) void attn_kernel()
{
    extern __shared__ __half sh[];

    int b  = blockIdx.y;
    int q0 = blockIdx.x * 128;
    const __half* t16 = d_t16 + (size_t)b * Nn * Fn;
    const __half* p16 = d_p16 + (size_t)b * Nn * Fn;
    const __half* g16 = d_g16 + (size_t)b * Fn * Nn;

    int tid  = threadIdx.x;
    int lane = tid & 31, warp = tid >> 5;
    int r = lane >> 2, cl = lane & 3;
    int qrow = warp * 16 + r;
    int lg = lane >> 3;
    int li = lane & 7;
    int rlo = (lg >> 1) * 8 + li;
    int koff = (lg & 1) * 8;

    // ---- theta fragments -> registers (one-time gmem read, pre-scaled) ----
    uint32_t th[8][4];
    {
        const __half* t0 = &t16[(size_t)(q0 + qrow) * Fn];
        const __half* t1 = &t16[(size_t)(q0 + qrow + 8) * Fn];
        #pragma unroll
        for (int kk = 0; kk < 8; kk++) {
            th[kk][0] = ldu32(&t0[kk * 16 + 2 * cl]);
            th[kk][1] = ldu32(&t1[kk * 16 + 2 * cl]);
            th[kk][2] = ldu32(&t0[kk * 16 + 2 * cl + 8]);
            th[kk][3] = ldu32(&t1[kk * 16 + 2 * cl + 8]);
        }
    }

    float oc[16][4];
    #pragma unroll
    for (int i = 0; i < 16; i++)
        #pragma unroll
        for (int j = 0; j < 4; j++) oc[i][j] = 0.f;

    float m0_ = -3.0e38f, m1_ = -3.0e38f;
    float l0_ = 0.f,      l1_ = 0.f;

    // ---- cp.async stage issue: 128 keys (256 threads, 16B each x16) ----
    auto issue = [&](int mb, int s) {
        __half* ph = sh + s * STAGE_HALVES;
        __half* gs = ph + PH_HALVES;
        #pragma unroll
        for (int i = 0; i < 8; i++) {
            int e = tid + i * 256;
            int m = e >> 4, c8 = (e & 15) * 8;
            cpa16(s2u(&ph[m * 136 + c8]), &p16[(size_t)(mb + m) * Fn + c8]);
        }
        #pragma unroll
        for (int i = 0; i < 8; i++) {
            int e = tid + i * 256;
            int f = e >> 4, c8 = (e & 15) * 8;
            cpa16(s2u(&gs[f * 136 + c8]), &g16[(size_t)f * Nn + mb + c8]);
        }
    };

    issue(0, 0);   CP_COMMIT();
    issue(128, 1); CP_COMMIT();

    const int NCH = Nn / 128;            // 32 stages
    for (int ic = 0; ic < NCH; ic++) {
        CP_WAIT1();
        __syncthreads();
        if (ic + 2 < NCH) issue((ic + 2) * 128, (ic + 2) % 3);
        CP_COMMIT();

        const __half* ph = sh + (ic % 3) * STAGE_HALVES;
        const __half* gs = ph + PH_HALVES;

        #pragma unroll
        for (int mh = 0; mh < 2; mh++) {      // two 64-key halves per stage
            const __half* phh = ph + mh * 64 * 136;
            int goff = mh * 64;

            // ---- S = theta phi^T : 16q x 64m ----
            float sc[8][4];
            #pragma unroll
            for (int i = 0; i < 8; i++)
                #pragma unroll
                for (int j = 0; j < 4; j++) sc[i][j] = 0.f;

            #pragma unroll
            for (int kk = 0; kk < 8; kk++) {
                uint32_t bf[16];
                #pragma unroll
                for (int p2 = 0; p2 < 4; p2++) {
                    ldsm4(bf[p2 * 4 + 0], bf[p2 * 4 + 1], bf[p2 * 4 + 2], bf[p2 * 4 + 3],
                          &phh[(p2 * 16 + rlo) * 136 + kk * 16 + koff]);
                }
                #pragma unroll
                for (int nt = 0; nt < 8; nt++) {
                    mma16(sc[nt], th[kk][0], th[kk][1], th[kk][2], th[kk][3],
                          bf[nt * 2], bf[nt * 2 + 1]);
                }
            }

            // ---- online softmax (exp2 domain, warp-local) ----
            float mx0 = -3.0e38f, mx1 = -3.0e38f;
            #pragma unroll
            for (int nt = 0; nt < 8; nt++) {
                mx0 = fmaxf(mx0, fmaxf(sc[nt][0], sc[nt][1]));
                mx1 = fmaxf(mx1, fmaxf(sc[nt][2], sc[nt][3]));
            }
            #pragma unroll
            for (int o = 1; o < 4; o <<= 1) {
                mx0 = fmaxf(mx0, __shfl_xor_sync(0xffffffffu, mx0, o));
                mx1 = fmaxf(mx1, __shfl_xor_sync(0xffffffffu, mx1, o));
            }
            float nm0 = fmaxf(m0_, mx0), nm1 = fmaxf(m1_, mx1);
            float al0 = exp2f(m0_ - nm0), al1 = exp2f(m1_ - nm1);
            m0_ = nm0; m1_ = nm1;

            uint32_t pp[8], pq[8];
            float rs0 = 0.f, rs1 = 0.f;
            #pragma unroll
            for (int nt = 0; nt < 8; nt++) {
                float p0 = exp2f(sc[nt][0] - nm0);
                float p1 = exp2f(sc[nt][1] - nm0);
                float p2 = exp2f(sc[nt][2] - nm1);
                float p3 = exp2f(sc[nt][3] - nm1);
                rs0 += p0 + p1; rs1 += p2 + p3;
                pp[nt] = packh2(p0, p1);
                pq[nt] = packh2(p2, p3);
            }
            #pragma unroll
            for (int o = 1; o < 4; o <<= 1) {
                rs0 += __shfl_xor_sync(0xffffffffu, rs0, o);
                rs1 += __shfl_xor_sync(0xffffffffu, rs1, o);
            }
            l0_ = l0_ * al0 + rs0;
            l1_ = l1_ * al1 + rs1;

            #pragma unroll
            for (int ft = 0; ft < 16; ft++) {
                oc[ft][0] *= al0; oc[ft][1] *= al0;
                oc[ft][2] *= al1; oc[ft][3] *= al1;
            }

            // ---- O += P G^T ----
            #pragma unroll
            for (int j = 0; j < 4; j++) {
                uint32_t a0 = pp[2 * j], a1 = pq[2 * j];
                uint32_t a2 = pp[2 * j + 1], a3 = pq[2 * j + 1];
                uint32_t gf[32];
                #pragma unroll
                for (int p2 = 0; p2 < 8; p2++) {
                    ldsm4(gf[p2 * 4 + 0], gf[p2 * 4 + 1], gf[p2 * 4 + 2], gf[p2 * 4 + 3],
                          &gs[(p2 * 16 + rlo) * 136 + goff + j * 16 + koff]);
                }
                #pragma unroll
                for (int ft = 0; ft < 16; ft++) {
                    mma16(oc[ft], a0, a1, a2, a3, gf[ft * 2], gf[ft * 2 + 1]);
                }
            }
        }
    }

    // ---- epilogue: normalize, write y [n][f] fp16 straight from registers ----
    float li0 = 1.0f / l0_, li1 = 1.0f / l1_;
    __half* yb = d_y16 + ((size_t)b * Nn + q0) * Fn;
    #pragma unroll
    for (int ft = 0; ft < 16; ft++) {
        int fb = ft * 8 + 2 * cl;
        *(__half2*)&yb[(size_t)qrow * Fn + fb] =
            __floats2half2_rn(oc[ft][0] * li0, oc[ft][1] * li0);
        *(__half2*)&yb[(size_t)(qrow + 8) * Fn + fb] =
            __floats2half2_rn(oc[ft][2] * li1, oc[ft][3] * li1);
    }
}

// ============================================================================
// kernel 3: z = Wz @ y + bz on fp16 mma (single K pass), LN partials fused
// ============================================================================
#define ZW_PITCH 136
#define ZY_PITCH 136
#define ZG_SMEM (128 * ZW_PITCH * 2 + 64 * ZY_PITCH * 2)

__global__ __launch_bounds__(256) void zgemm_mma(const float* __restrict__ bz)
{
    extern __shared__ char zsm[];
    __half* Ws = (__half*)zsm;                        // [128][136]
    __half* Ys = (__half*)(zsm + 128 * ZW_PITCH * 2); // [64][136]

    int b  = blockIdx.z;
    int m0 = blockIdx.y * 128;
    int n0 = blockIdx.x * 64;
    const __half* W16z = d_w16 + (size_t)3 * 32768;   // [256][128]
    const __half* Y16 = d_y16 + (size_t)b * Nn * Fn;
    float* Z = d_z + (size_t)b * CINn * Nn;

    int tid = threadIdx.x;
    int lane = tid & 31, warp = tid >> 5;
    int r = lane >> 2, cl = lane & 3;
    int qrow = warp * 16 + r;

    #pragma unroll
    for (int e = tid; e < 128 * 16; e += 256) {
        int m = e >> 4, c8 = (e & 15) * 8;
        *(uint4*)&Ws[m * ZW_PITCH + c8] =
            *(const uint4*)&W16z[(size_t)(m0 + m) * Fn + c8];
    }
    #pragma unroll
    for (int e = tid; e < 64 * 16; e += 256) {
        int n = e >> 4, c8 = (e & 15) * 8;
        *(uint4*)&Ys[n * ZY_PITCH + c8] = *(const uint4*)&Y16[(size_t)(n0 + n) * Fn + c8];
    }
    __syncthreads();

    float acc[8][4];
    #pragma unroll
    for (int i = 0; i < 8; i++)
        #pragma unroll
        for (int j = 0; j < 4; j++) acc[i][j] = 0.f;

    #pragma unroll
    for (int kk = 0; kk < Fn; kk += 16) {
        uint32_t a0 = ldu32(&Ws[qrow       * ZW_PITCH + kk + 2 * cl    ]);
        uint32_t a1 = ldu32(&Ws[(qrow + 8) * ZW_PITCH + kk + 2 * cl    ]);
        uint32_t a2 = ldu32(&Ws[qrow       * ZW_PITCH + kk + 2 * cl + 8]);
        uint32_t a3 = ldu32(&Ws[(qrow + 8) * ZW_PITCH + kk + 2 * cl + 8]);
        #pragma unroll
        for (int nt = 0; nt < 8; nt++) {
            int nc = nt * 8 + r;
            uint32_t b0 = ldu32(&Ys[nc * ZY_PITCH + kk + 2 * cl    ]);
            uint32_t b1 = ldu32(&Ys[nc * ZY_PITCH + kk + 2 * cl + 8]);
            mma16(acc[nt], a0, a1, a2, a3, b0, b1);
        }
    }
    __syncthreads();

    float bi0 = bz[m0 + qrow], bi1 = bz[m0 + qrow + 8];
    float lsum = 0.f, lsq = 0.f;
    #pragma unroll
    for (int nt = 0; nt < 8; nt++) {
        int nc = n0 + nt * 8 + 2 * cl;
        float v0 = acc[nt][0] + bi0, v1 = acc[nt][1] + bi0;
        float v2 = acc[nt][2] + bi1, v3 = acc[nt][3] + bi1;
        *(float2*)&Z[(size_t)(m0 + qrow) * Nn + nc]     = make_float2(v0, v1);
        *(float2*)&Z[(size_t)(m0 + qrow + 8) * Nn + nc] = make_float2(v2, v3);
        lsum += v0 + v1 + v2 + v3;
        lsq  += v0 * v0 + v1 * v1 + v2 * v2 + v3 * v3;
    }

    float* rs = (float*)zsm;
    float* rq = rs + 256;
    rs[tid] = lsum; rq[tid] = lsq;
    __syncthreads();
    #pragma unroll
    for (int s = 128; s > 0; s >>= 1) {
        if (tid < s) { rs[tid] += rs[tid + s]; rq[tid] += rq[tid + s]; }
        __syncthreads();
    }
    if (tid == 0) {
        int idx = b * 128 + blockIdx.y * 64 + blockIdx.x;
        d_part[2 * idx]     = rs[0];
        d_part[2 * idx + 1] = rq[0];
    }
}

// ---------------- kernel 4: per-batch mean / rsig ---------------------------
__global__ __launch_bounds__(128) void stats_kernel()
{
    int b = blockIdx.x;
    int tid = threadIdx.x;
    __shared__ float rs[128], rq[128];
    int idx = b * 128 + tid;
    rs[tid] = d_part[2 * idx];
    rq[tid] = d_part[2 * idx + 1];
    __syncthreads();
    #pragma unroll
    for (int s = 64; s > 0; s >>= 1) {
        if (tid < s) { rs[tid] += rs[tid + s]; rq[tid] += rq[tid + s]; }
        __syncthreads();
    }
    if (tid == 0) {
        float inv = 1.0f / ((float)CINn * (float)Nn);
        float mu  = rs[0] * inv;
        float var = rq[0] * inv - mu * mu;
        d_stats[2 * b]     = mu;
        d_stats[2 * b + 1] = rsqrtf(var + EPSc);
    }
}

// ---------------- kernel 5: LN affine + residual ----------------------------
__global__ __launch_bounds__(256) void finalize_kernel(
    const float* __restrict__ x, const float* __restrict__ lw,
    const float* __restrict__ lb, float* __restrict__ out)
{
    const int per_b4 = CINn * Nn / 4;
    const int tot4   = Bn * per_b4;
    for (int i = blockIdx.x * blockDim.x + threadIdx.x; i < tot4;
         i += gridDim.x * blockDim.x) {
        int b = i / per_b4;
        int r = i - b * per_b4;
        float mu   = d_stats[2 * b];
        float rsig = d_stats[2 * b + 1];
        float4 z  = ((const float4*)d_z)[i];
        float4 xv = ((const float4*)x)[i];
        float4 w  = ((const float4*)lw)[r];
        float4 bb = ((const float4*)lb)[r];
        float4 o;
        o.x = (z.x - mu) * rsig * w.x + bb.x + xv.x;
        o.y = (z.y - mu) * rsig * w.y + bb.y + xv.y;
        o.z = (z.z - mu) * rsig * w.z + bb.z + xv.z;
        o.w = (z.w - mu) * rsig * w.w + bb.w + xv.w;
        ((float4*)out)[i] = o;
    }
}

// ---------------- launch -----------------------------------------------------
extern "C" void kernel_launch(void* const* d_in, const int* in_sizes, int n_in,
                              void* d_out, int out_size)
{
    const float* x   = (const float*)d_in[0];
    const float* Wg  = (const float*)d_in[1];
    const float* bg  = (const float*)d_in[2];
    const float* Wt  = (const float*)d_in[3];
    const float* bt  = (const float*)d_in[4];
    const float* Wp  = (const float*)d_in[5];
    const float* bp  = (const float*)d_in[6];
    const float* Wz  = (const float*)d_in[7];
    const float* bz  = (const float*)d_in[8];
    const float* lnw = (const float*)d_in[9];
    const float* lnb = (const float*)d_in[10];
    float* out = (float*)d_out;

    cudaFuncSetAttribute(attn_kernel, cudaFuncAttributeMaxDynamicSharedMemorySize,
                         ATTN_SMEM);
    cudaFuncSetAttribute(proj_mma, cudaFuncAttributeMaxDynamicSharedMemorySize,
                         PROJ_SMEM);
    cudaFuncSetAttribute(zgemm_mma, cudaFuncAttributeMaxDynamicSharedMemorySize,
                         ZG_SMEM);

    prep_w<<<128, 256>>>(Wg, Wt, Wp, Wz);
    xpose<<<dim3(128, 4, 4), 256>>>(x);
    proj_mma<<<dim3(64, 12), 256, PROJ_SMEM>>>(bg, bt, bp);
    attn_kernel<<<dim3(32, 4), 256, ATTN_SMEM>>>();
    zgemm_mma<<<dim3(64, 2, 4), 256, ZG_SMEM>>>(bz);
    stats_kernel<<<4, 128>>>();
    finalize_kernel<<<4096, 256>>>(x, lnw, lnb, out);
}

// round 15
// speedup vs baseline: 1.3088x; 1.0216x over previous
#include <cuda_runtime.h>
#include <cuda_fp16.h>
#include <math.h>
#include <stdint.h>

#define Bn   4
#define CINn 256
#define Fn   128
#define Nn   4096
#define EPSc 1e-5f
#define LOG2E 1.4426950408889634f
#define ONES_H2 0x3C003C00u

// ---------------- scratch (device globals: no allocation allowed) ----------
__device__ __half d_x16[(size_t)Bn * Nn * CINn];  // x transposed [b][n][c] fp16
__device__ __half d_w16[4 * 32768];               // Wg,Wt,Wp [128][256]; Wz [256][128]
__device__ __half d_t16[(size_t)Bn * Nn * Fn];    // theta*log2e, [b][n][f]
__device__ __half d_p16[(size_t)Bn * Nn * Fn];    // phi,   [b][n][f]
__device__ __half d_g16[(size_t)Bn * Fn * Nn];    // g,     [b][f][n]
__device__ __half d_y16[(size_t)Bn * Nn * Fn];    // y,     [b][n][f]
__device__ float  d_z[(size_t)Bn * CINn * Nn];    // pre-LN output [b][c][n]
__device__ float  d_part[2 * Bn * 128];           // per-tile (sum,sumsq) partials
__device__ float  d_stats[2 * Bn];                // per-batch (mu, rsig)

// ---------------- helpers ---------------------------------------------------
__device__ __forceinline__ void mma16(float c[4],
        uint32_t a0, uint32_t a1, uint32_t a2, uint32_t a3,
        uint32_t b0, uint32_t b1) {
    asm volatile(
        "mma.sync.aligned.m16n8k16.row.col.f32.f16.f16.f32 "
        "{%0,%1,%2,%3}, {%4,%5,%6,%7}, {%8,%9}, {%0,%1,%2,%3};\n"
        : "+f"(c[0]), "+f"(c[1]), "+f"(c[2]), "+f"(c[3])
        : "r"(a0), "r"(a1), "r"(a2), "r"(a3), "r"(b0), "r"(b1));
}
__device__ __forceinline__ uint32_t ldu32(const __half* p) {
    return *(const uint32_t*)p;
}
__device__ __forceinline__ uint32_t packh2(float a, float b) {
    __half2 h = __floats2half2_rn(a, b);
    return *(uint32_t*)&h;
}
__device__ __forceinline__ uint32_t h2exp2(uint32_t x) {
    uint32_t r;
    asm("ex2.approx.f16x2 %0, %1;" : "=r"(r) : "r"(x));
    return r;
}
__device__ __forceinline__ void cpa16(uint32_t dst, const void* src) {
    asm volatile("cp.async.cg.shared.global [%0], [%1], 16;" :: "r"(dst), "l"(src));
}
#define CP_COMMIT() asm volatile("cp.async.commit_group;")
#define CP_WAIT1()  asm volatile("cp.async.wait_group 1;")
__device__ __forceinline__ uint32_t s2u(const void* p) {
    return (uint32_t)__cvta_generic_to_shared(p);
}
__device__ __forceinline__ void ldsm4(uint32_t& r0, uint32_t& r1,
                                      uint32_t& r2, uint32_t& r3,
                                      const __half* addr) {
    asm volatile("ldmatrix.sync.aligned.m8n8.x4.shared.b16 {%0,%1,%2,%3}, [%4];"
        : "=r"(r0), "=r"(r1), "=r"(r2), "=r"(r3) : "r"(s2u(addr)));
}

// ============================================================================
// kernel 0a: convert the four weight matrices to fp16 (once per launch)
// ============================================================================
__global__ __launch_bounds__(256) void prep_w(
    const float* __restrict__ Wg, const float* __restrict__ Wt,
    const float* __restrict__ Wp, const float* __restrict__ Wz)
{
    const float* srcs[4] = {Wg, Wt, Wp, Wz};
    int stride = gridDim.x * blockDim.x;
    for (int i = blockIdx.x * blockDim.x + threadIdx.x; i < 4 * 8192; i += stride) {
        int w = i >> 13;
        int e = i & 8191;
        float4 v = ((const float4*)srcs[w])[e];
        *(__half2*)&d_w16[(size_t)w * 32768 + e * 4]     = __floats2half2_rn(v.x, v.y);
        *(__half2*)&d_w16[(size_t)w * 32768 + e * 4 + 2] = __floats2half2_rn(v.z, v.w);
    }
}

// ============================================================================
// kernel 0b: transpose x [b][c][n] fp32 -> d_x16 [b][n][c] fp16
// ============================================================================
__global__ __launch_bounds__(256) void xpose(const float* __restrict__ x)
{
    __shared__ float t[64][33];
    int b  = blockIdx.z;
    int c0 = blockIdx.y * 64;
    int n0 = blockIdx.x * 32;
    const float* X = x + ((size_t)b * CINn + c0) * Nn;
    int tid = threadIdx.x;
    int tn = tid & 31, tc = tid >> 5;

    #pragma unroll
    for (int cc = tc; cc < 64; cc += 8)
        t[cc][tn] = X[(size_t)cc * Nn + n0 + tn];
    __syncthreads();

    int lane = tid & 31, warp = tid >> 5;
    __half* out = d_x16 + ((size_t)b * Nn + n0) * CINn + c0;
    #pragma unroll
    for (int nn = warp; nn < 32; nn += 8) {
        float v0 = t[2 * lane][nn], v1 = t[2 * lane + 1][nn];
        *(__half2*)&out[(size_t)nn * CINn + 2 * lane] = __floats2half2_rn(v0, v1);
    }
}

// ============================================================================
// kernel 1: the three 1x1-conv GEMMs on fp16 mma, K=256 fully resident
//   theta output pre-scaled by log2(e) for exp2-domain softmax.
// ============================================================================
#define PW_PITCH 264
#define PROJ_SMEM ((128 + 64) * PW_PITCH * 2)

__global__ __launch_bounds__(256) void proj_mma(
    const float* __restrict__ bg, const float* __restrict__ bt,
    const float* __restrict__ bp)
{
    extern __shared__ char psm[];
    __half* Ws = (__half*)psm;                        // [128][264]
    __half* Xs = (__half*)(psm + 128 * PW_PITCH * 2); // [64][264]

    int pb   = blockIdx.y;
    int proj = pb % 3;
    int b    = pb / 3;
    const __half* Wm = d_w16 + (size_t)proj * 32768;
    const float* bias = (proj == 0) ? bg : (proj == 1 ? bt : bp);

    const __half* X16 = d_x16 + (size_t)b * Nn * CINn;
    int n0 = blockIdx.x * 64;

    int tid = threadIdx.x;
    int lane = tid & 31, warp = tid >> 5;
    int r = lane >> 2, cl = lane & 3;
    int qrow = warp * 16 + r;

    #pragma unroll
    for (int e = tid; e < 128 * 32; e += 256) {
        int m = e >> 5, c8 = (e & 31) * 8;
        *(uint4*)&Ws[m * PW_PITCH + c8] = *(const uint4*)&Wm[(size_t)m * 256 + c8];
    }
    #pragma unroll
    for (int e = tid; e < 64 * 32; e += 256) {
        int n = e >> 5, c8 = (e & 31) * 8;
        *(uint4*)&Xs[n * PW_PITCH + c8] =
            *(const uint4*)&X16[(size_t)(n0 + n) * CINn + c8];
    }
    __syncthreads();

    float acc[8][4];
    #pragma unroll
    for (int i = 0; i < 8; i++)
        #pragma unroll
        for (int j = 0; j < 4; j++) acc[i][j] = 0.f;

    #pragma unroll
    for (int kk = 0; kk < CINn; kk += 16) {
        uint32_t a0 = ldu32(&Ws[qrow       * PW_PITCH + kk + 2 * cl    ]);
        uint32_t a1 = ldu32(&Ws[(qrow + 8) * PW_PITCH + kk + 2 * cl    ]);
        uint32_t a2 = ldu32(&Ws[qrow       * PW_PITCH + kk + 2 * cl + 8]);
        uint32_t a3 = ldu32(&Ws[(qrow + 8) * PW_PITCH + kk + 2 * cl + 8]);
        #pragma unroll
        for (int nt = 0; nt < 8; nt++) {
            int nc = nt * 8 + r;
            uint32_t b0 = ldu32(&Xs[nc * PW_PITCH + kk + 2 * cl    ]);
            uint32_t b1 = ldu32(&Xs[nc * PW_PITCH + kk + 2 * cl + 8]);
            mma16(acc[nt], a0, a1, a2, a3, b0, b1);
        }
    }

    float bi0 = bias[qrow], bi1 = bias[qrow + 8];
    if (proj == 0) {
        __half* out = d_g16 + (size_t)b * Fn * Nn;
        #pragma unroll
        for (int nt = 0; nt < 8; nt++) {
            int nc = n0 + nt * 8 + 2 * cl;
            *(__half2*)&out[(size_t)qrow * Nn + nc] =
                __floats2half2_rn(acc[nt][0] + bi0, acc[nt][1] + bi0);
            *(__half2*)&out[(size_t)(qrow + 8) * Nn + nc] =
                __floats2half2_rn(acc[nt][2] + bi1, acc[nt][3] + bi1);
        }
    } else {
        __half* out = (proj == 1 ? d_t16 : d_p16) + (size_t)b * Nn * Fn;
        float sc = (proj == 1) ? LOG2E : 1.0f;
        #pragma unroll
        for (int nt = 0; nt < 8; nt++) {
            int nc = n0 + nt * 8 + 2 * cl;
            out[(size_t)nc       * Fn + qrow    ] = __float2half_rn((acc[nt][0] + bi0) * sc);
            out[(size_t)(nc + 1) * Fn + qrow    ] = __float2half_rn((acc[nt][1] + bi0) * sc);
            out[(size_t)nc       * Fn + qrow + 8] = __float2half_rn((acc[nt][2] + bi1) * sc);
            out[(size_t)(nc + 1) * Fn + qrow + 8] = __float2half_rn((acc[nt][3] + bi1) * sc);
        }
    }
}

// ============================================================================
// kernel 2: fused flash attention, fp16 mma, 128-key stages, 3-stage cp.async,
//   theta + P in registers, ldmatrix.x4 B frags, one barrier per 128 keys.
//   Softmax: exp2-domain, ex2.approx.f16x2 (half the MUFU ops), row sums via
//   an extra mma against a ones-fragment (no shfl reduction, fp32-exact).
// ============================================================================
#define PH_HALVES (128 * 136)          // phi stage  [m][f],   m-chunk 128
#define GS_HALVES (128 * 136)          // g   stage  [f][m],   m-chunk 128
#define STAGE_HALVES (PH_HALVES + GS_HALVES)
#define ATTN_SMEM (3 * STAGE_HALVES * 2)

__global__ __launch_bounds__(256, 1) void attn_kernel()
{
    extern __shared__ __half sh[];

    int b  = blockIdx.y;
    int q0 = blockIdx.x * 128;
    const __half* t16 = d_t16 + (size_t)b * Nn * Fn;
    const __half* p16 = d_p16 + (size_t)b * Nn * Fn;
    const __half* g16 = d_g16 + (size_t)b * Fn * Nn;

    int tid  = threadIdx.x;
    int lane = tid & 31, warp = tid >> 5;
    int r = lane >> 2, cl = lane & 3;
    int qrow = warp * 16 + r;
    int lg = lane >> 3;
    int li = lane & 7;
    int rlo = (lg >> 1) * 8 + li;
    int koff = (lg & 1) * 8;

    // ---- theta fragments -> registers (one-time gmem read, pre-scaled) ----
    uint32_t th[8][4];
    {
        const __half* t0 = &t16[(size_t)(q0 + qrow) * Fn];
        const __half* t1 = &t16[(size_t)(q0 + qrow + 8) * Fn];
        #pragma unroll
        for (int kk = 0; kk < 8; kk++) {
            th[kk][0] = ldu32(&t0[kk * 16 + 2 * cl]);
            th[kk][1] = ldu32(&t1[kk * 16 + 2 * cl]);
            th[kk][2] = ldu32(&t0[kk * 16 + 2 * cl + 8]);
            th[kk][3] = ldu32(&t1[kk * 16 + 2 * cl + 8]);
        }
    }

    float oc[16][4];
    #pragma unroll
    for (int i = 0; i < 16; i++)
        #pragma unroll
        for (int j = 0; j < 4; j++) oc[i][j] = 0.f;

    float m0_ = -3.0e38f, m1_ = -3.0e38f;
    float l0_ = 0.f,      l1_ = 0.f;

    // ---- cp.async stage issue: 128 keys (256 threads, 16B each x16) ----
    auto issue = [&](int mb, int s) {
        __half* ph = sh + s * STAGE_HALVES;
        __half* gs = ph + PH_HALVES;
        #pragma unroll
        for (int i = 0; i < 8; i++) {
            int e = tid + i * 256;
            int m = e >> 4, c8 = (e & 15) * 8;
            cpa16(s2u(&ph[m * 136 + c8]), &p16[(size_t)(mb + m) * Fn + c8]);
        }
        #pragma unroll
        for (int i = 0; i < 8; i++) {
            int e = tid + i * 256;
            int f = e >> 4, c8 = (e & 15) * 8;
            cpa16(s2u(&gs[f * 136 + c8]), &g16[(size_t)f * Nn + mb + c8]);
        }
    };

    issue(0, 0);   CP_COMMIT();
    issue(128, 1); CP_COMMIT();

    const int NCH = Nn / 128;            // 32 stages
    for (int ic = 0; ic < NCH; ic++) {
        CP_WAIT1();
        __syncthreads();
        if (ic + 2 < NCH) issue((ic + 2) * 128, (ic + 2) % 3);
        CP_COMMIT();

        const __half* ph = sh + (ic % 3) * STAGE_HALVES;
        const __half* gs = ph + PH_HALVES;

        #pragma unroll
        for (int mh = 0; mh < 2; mh++) {      // two 64-key halves per stage
            const __half* phh = ph + mh * 64 * 136;
            int goff = mh * 64;

            // ---- S = theta phi^T : 16q x 64m ----
            float sc[8][4];
            #pragma unroll
            for (int i = 0; i < 8; i++)
                #pragma unroll
                for (int j = 0; j < 4; j++) sc[i][j] = 0.f;

            #pragma unroll
            for (int kk = 0; kk < 8; kk++) {
                uint32_t bf[16];
                #pragma unroll
                for (int p2 = 0; p2 < 4; p2++) {
                    ldsm4(bf[p2 * 4 + 0], bf[p2 * 4 + 1], bf[p2 * 4 + 2], bf[p2 * 4 + 3],
                          &phh[(p2 * 16 + rlo) * 136 + kk * 16 + koff]);
                }
                #pragma unroll
                for (int nt = 0; nt < 8; nt++) {
                    mma16(sc[nt], th[kk][0], th[kk][1], th[kk][2], th[kk][3],
                          bf[nt * 2], bf[nt * 2 + 1]);
                }
            }

            // ---- online softmax (exp2 domain, fp16x2 MUFU, no sum-shfl) ----
            float mx0 = -3.0e38f, mx1 = -3.0e38f;
            #pragma unroll
            for (int nt = 0; nt < 8; nt++) {
                mx0 = fmaxf(mx0, fmaxf(sc[nt][0], sc[nt][1]));
                mx1 = fmaxf(mx1, fmaxf(sc[nt][2], sc[nt][3]));
            }
            #pragma unroll
            for (int o = 1; o < 4; o <<= 1) {
                mx0 = fmaxf(mx0, __shfl_xor_sync(0xffffffffu, mx0, o));
                mx1 = fmaxf(mx1, __shfl_xor_sync(0xffffffffu, mx1, o));
            }
            float nm0 = fmaxf(m0_, mx0), nm1 = fmaxf(m1_, mx1);
            float al0 = exp2f(m0_ - nm0), al1 = exp2f(m1_ - nm1);
            m0_ = nm0; m1_ = nm1;

            uint32_t pp[8], pq[8];
            #pragma unroll
            for (int nt = 0; nt < 8; nt++) {
                pp[nt] = h2exp2(packh2(sc[nt][0] - nm0, sc[nt][1] - nm0));
                pq[nt] = h2exp2(packh2(sc[nt][2] - nm1, sc[nt][3] - nm1));
            }

            #pragma unroll
            for (int ft = 0; ft < 16; ft++) {
                oc[ft][0] *= al0; oc[ft][1] *= al0;
                oc[ft][2] *= al1; oc[ft][3] *= al1;
            }

            // ---- O += P G^T ; row sums via ones-fragment mma ----
            float lc[4] = {0.f, 0.f, 0.f, 0.f};
            #pragma unroll
            for (int j = 0; j < 4; j++) {
                uint32_t a0 = pp[2 * j], a1 = pq[2 * j];
                uint32_t a2 = pp[2 * j + 1], a3 = pq[2 * j + 1];
                mma16(lc, a0, a1, a2, a3, ONES_H2, ONES_H2);
                uint32_t gf[32];
                #pragma unroll
                for (int p2 = 0; p2 < 8; p2++) {
                    ldsm4(gf[p2 * 4 + 0], gf[p2 * 4 + 1], gf[p2 * 4 + 2], gf[p2 * 4 + 3],
                          &gs[(p2 * 16 + rlo) * 136 + goff + j * 16 + koff]);
                }
                #pragma unroll
                for (int ft = 0; ft < 16; ft++) {
                    mma16(oc[ft], a0, a1, a2, a3, gf[ft * 2], gf[ft * 2 + 1]);
                }
            }
            l0_ = l0_ * al0 + lc[0];
            l1_ = l1_ * al1 + lc[2];
        }
    }

    // ---- epilogue: normalize, write y [n][f] fp16 straight from registers ----
    float li0 = 1.0f / l0_, li1 = 1.0f / l1_;
    __half* yb = d_y16 + ((size_t)b * Nn + q0) * Fn;
    #pragma unroll
    for (int ft = 0; ft < 16; ft++) {
        int fb = ft * 8 + 2 * cl;
        *(__half2*)&yb[(size_t)qrow * Fn + fb] =
            __floats2half2_rn(oc[ft][0] * li0, oc[ft][1] * li0);
        *(__half2*)&yb[(size_t)(qrow + 8) * Fn + fb] =
            __floats2half2_rn(oc[ft][2] * li1, oc[ft][3] * li1);
    }
}

// ============================================================================
// kernel 3: z = Wz @ y + bz on fp16 mma (single K pass), LN partials fused
// ============================================================================
#define ZW_PITCH 136
#define ZY_PITCH 136
#define ZG_SMEM (128 * ZW_PITCH * 2 + 64 * ZY_PITCH * 2)

__global__ __launch_bounds__(256) void zgemm_mma(const float* __restrict__ bz)
{
    extern __shared__ char zsm[];
    __half* Ws = (__half*)zsm;                        // [128][136]
    __half* Ys = (__half*)(zsm + 128 * ZW_PITCH * 2); // [64][136]

    int b  = blockIdx.z;
    int m0 = blockIdx.y * 128;
    int n0 = blockIdx.x * 64;
    const __half* W16z = d_w16 + (size_t)3 * 32768;   // [256][128]
    const __half* Y16 = d_y16 + (size_t)b * Nn * Fn;
    float* Z = d_z + (size_t)b * CINn * Nn;

    int tid = threadIdx.x;
    int lane = tid & 31, warp = tid >> 5;
    int r = lane >> 2, cl = lane & 3;
    int qrow = warp * 16 + r;

    #pragma unroll
    for (int e = tid; e < 128 * 16; e += 256) {
        int m = e >> 4, c8 = (e & 15) * 8;
        *(uint4*)&Ws[m * ZW_PITCH + c8] =
            *(const uint4*)&W16z[(size_t)(m0 + m) * Fn + c8];
    }
    #pragma unroll
    for (int e = tid; e < 64 * 16; e += 256) {
        int n = e >> 4, c8 = (e & 15) * 8;
        *(uint4*)&Ys[n * ZY_PITCH + c8] = *(const uint4*)&Y16[(size_t)(n0 + n) * Fn + c8];
    }
    __syncthreads();

    float acc[8][4];
    #pragma unroll
    for (int i = 0; i < 8; i++)
        #pragma unroll
        for (int j = 0; j < 4; j++) acc[i][j] = 0.f;

    #pragma unroll
    for (int kk = 0; kk < Fn; kk += 16) {
        uint32_t a0 = ldu32(&Ws[qrow       * ZW_PITCH + kk + 2 * cl    ]);
        uint32_t a1 = ldu32(&Ws[(qrow + 8) * ZW_PITCH + kk + 2 * cl    ]);
        uint32_t a2 = ldu32(&Ws[qrow       * ZW_PITCH + kk + 2 * cl + 8]);
        uint32_t a3 = ldu32(&Ws[(qrow + 8) * ZW_PITCH + kk + 2 * cl + 8]);
        #pragma unroll
        for (int nt = 0; nt < 8; nt++) {
            int nc = nt * 8 + r;
            uint32_t b0 = ldu32(&Ys[nc * ZY_PITCH + kk + 2 * cl    ]);
            uint32_t b1 = ldu32(&Ys[nc * ZY_PITCH + kk + 2 * cl + 8]);
            mma16(acc[nt], a0, a1, a2, a3, b0, b1);
        }
    }
    __syncthreads();

    float bi0 = bz[m0 + qrow], bi1 = bz[m0 + qrow + 8];
    float lsum = 0.f, lsq = 0.f;
    #pragma unroll
    for (int nt = 0; nt < 8; nt++) {
        int nc = n0 + nt * 8 + 2 * cl;
        float v0 = acc[nt][0] + bi0, v1 = acc[nt][1] + bi0;
        float v2 = acc[nt][2] + bi1, v3 = acc[nt][3] + bi1;
        *(float2*)&Z[(size_t)(m0 + qrow) * Nn + nc]     = make_float2(v0, v1);
        *(float2*)&Z[(size_t)(m0 + qrow + 8) * Nn + nc] = make_float2(v2, v3);
        lsum += v0 + v1 + v2 + v3;
        lsq  += v0 * v0 + v1 * v1 + v2 * v2 + v3 * v3;
    }

    float* rs = (float*)zsm;
    float* rq = rs + 256;
    rs[tid] = lsum; rq[tid] = lsq;
    __syncthreads();
    #pragma unroll
    for (int s = 128; s > 0; s >>= 1) {
        if (tid < s) { rs[tid] += rs[tid + s]; rq[tid] += rq[tid + s]; }
        __syncthreads();
    }
    if (tid == 0) {
        int idx = b * 128 + blockIdx.y * 64 + blockIdx.x;
        d_part[2 * idx]     = rs[0];
        d_part[2 * idx + 1] = rq[0];
    }
}

// ---------------- kernel 4: per-batch mean / rsig ---------------------------
__global__ __launch_bounds__(128) void stats_kernel()
{
    int b = blockIdx.x;
    int tid = threadIdx.x;
    __shared__ float rs[128], rq[128];
    int idx = b * 128 + tid;
    rs[tid] = d_part[2 * idx];
    rq[tid] = d_part[2 * idx + 1];
    __syncthreads();
    #pragma unroll
    for (int s = 64; s > 0; s >>= 1) {
        if (tid < s) { rs[tid] += rs[tid + s]; rq[tid] += rq[tid + s]; }
        __syncthreads();
    }
    if (tid == 0) {
        float inv = 1.0f / ((float)CINn * (float)Nn);
        float mu  = rs[0] * inv;
        float var = rq[0] * inv - mu * mu;
        d_stats[2 * b]     = mu;
        d_stats[2 * b + 1] = rsqrtf(var + EPSc);
    }
}

// ---------------- kernel 5: LN affine + residual ----------------------------
__global__ __launch_bounds__(256) void finalize_kernel(
    const float* __restrict__ x, const float* __restrict__ lw,
    const float* __restrict__ lb, float* __restrict__ out)
{
    const int per_b4 = CINn * Nn / 4;
    const int tot4   = Bn * per_b4;
    for (int i = blockIdx.x * blockDim.x + threadIdx.x; i < tot4;
         i += gridDim.x * blockDim.x) {
        int b = i / per_b4;
        int r = i - b * per_b4;
        float mu   = d_stats[2 * b];
        float rsig = d_stats[2 * b + 1];
        float4 z  = ((const float4*)d_z)[i];
        float4 xv = ((const float4*)x)[i];
        float4 w  = ((const float4*)lw)[r];
        float4 bb = ((const float4*)lb)[r];
        float4 o;
        o.x = (z.x - mu) * rsig * w.x + bb.x + xv.x;
        o.y = (z.y - mu) * rsig * w.y + bb.y + xv.y;
        o.z = (z.z - mu) * rsig * w.z + bb.z + xv.z;
        o.w = (z.w - mu) * rsig * w.w + bb.w + xv.w;
        ((float4*)out)[i] = o;
    }
}

// ---------------- launch -----------------------------------------------------
extern "C" void kernel_launch(void* const* d_in, const int* in_sizes, int n_in,
                              void* d_out, int out_size)
{
    const float* x   = (const float*)d_in[0];
    const float* Wg  = (const float*)d_in[1];
    const float* bg  = (const float*)d_in[2];
    const float* Wt  = (const float*)d_in[3];
    const float* bt  = (const float*)d_in[4];
    const float* Wp  = (const float*)d_in[5];
    const float* bp  = (const float*)d_in[6];
    const float* Wz  = (const float*)d_in[7];
    const float* bz  = (const float*)d_in[8];
    const float* lnw = (const float*)d_in[9];
    const float* lnb = (const float*)d_in[10];
    float* out = (float*)d_out;

    cudaFuncSetAttribute(attn_kernel, cudaFuncAttributeMaxDynamicSharedMemorySize,
                         ATTN_SMEM);
    cudaFuncSetAttribute(proj_mma, cudaFuncAttributeMaxDynamicSharedMemorySize,
                         PROJ_SMEM);
    cudaFuncSetAttribute(zgemm_mma, cudaFuncAttributeMaxDynamicSharedMemorySize,
                         ZG_SMEM);

    prep_w<<<128, 256>>>(Wg, Wt, Wp, Wz);
    xpose<<<dim3(128, 4, 4), 256>>>(x);
    proj_mma<<<dim3(64, 12), 256, PROJ_SMEM>>>(bg, bt, bp);
    attn_kernel<<<dim3(32, 4), 256, ATTN_SMEM>>>();
    zgemm_mma<<<dim3(64, 2, 4), 256, ZG_SMEM>>>(bz);
    stats_kernel<<<4, 128>>>();
    finalize_kernel<<<4096, 256>>>(x, lnw, lnb, out);
}

// round 16
// speedup vs baseline: 1.3255x; 1.0127x over previous
#include <cuda_runtime.h>
#include <cuda_fp16.h>
#include <math.h>
#include <stdint.h>

#define Bn   4
#define CINn 256
#define Fn   128
#define Nn   4096
#define EPSc 1e-5f
#define LOG2E 1.4426950408889634f
#define ONES_H2 0x3C003C00u

// ---------------- scratch (device globals: no allocation allowed) ----------
__device__ __half d_x16[(size_t)Bn * Nn * CINn];  // x transposed [b][n][c] fp16
__device__ __half d_w16[4 * 32768];               // Wg,Wt,Wp [128][256]; Wz [256][128]
__device__ __half d_t16[(size_t)Bn * Nn * Fn];    // theta*log2e, [b][n][f]
__device__ __half d_p16[(size_t)Bn * Nn * Fn];    // phi,   [b][n][f]
__device__ __half d_g16[(size_t)Bn * Fn * Nn];    // g,     [b][f][n]
__device__ __half d_y16[(size_t)Bn * Nn * Fn];    // y,     [b][n][f]
__device__ float  d_z[(size_t)Bn * CINn * Nn];    // pre-LN output [b][c][n]
__device__ float  d_part[2 * Bn * 128];           // per-tile (sum,sumsq) partials
__device__ float  d_stats[2 * Bn];                // per-batch (mu, rsig)

// ---------------- helpers ---------------------------------------------------
__device__ __forceinline__ void mma16(float c[4],
        uint32_t a0, uint32_t a1, uint32_t a2, uint32_t a3,
        uint32_t b0, uint32_t b1) {
    asm volatile(
        "mma.sync.aligned.m16n8k16.row.col.f32.f16.f16.f32 "
        "{%0,%1,%2,%3}, {%4,%5,%6,%7}, {%8,%9}, {%0,%1,%2,%3};\n"
        : "+f"(c[0]), "+f"(c[1]), "+f"(c[2]), "+f"(c[3])
        : "r"(a0), "r"(a1), "r"(a2), "r"(a3), "r"(b0), "r"(b1));
}
__device__ __forceinline__ uint32_t ldu32(const __half* p) {
    return *(const uint32_t*)p;
}
__device__ __forceinline__ uint32_t packh2(float a, float b) {
    __half2 h = __floats2half2_rn(a, b);
    return *(uint32_t*)&h;
}
__device__ __forceinline__ uint32_t h2exp2(uint32_t x) {
    uint32_t r;
    asm("ex2.approx.f16x2 %0, %1;" : "=r"(r) : "r"(x));
    return r;
}
__device__ __forceinline__ uint32_t h2max(uint32_t a, uint32_t b) {
    __half2 r = __hmax2(*(__half2*)&a, *(__half2*)&b);
    return *(uint32_t*)&r;
}
__device__ __forceinline__ uint32_t h2sub(uint32_t a, uint32_t b) {
    __half2 r = __hsub2(*(__half2*)&a, *(__half2*)&b);
    return *(uint32_t*)&r;
}
__device__ __forceinline__ void mulx2(float* p, unsigned long long s) {
    asm("mul.rn.f32x2 %0, %0, %1;" : "+l"(*(unsigned long long*)p) : "l"(s));
}
__device__ __forceinline__ unsigned long long packf2(float a, float b) {
    unsigned long long r;
    asm("mov.b64 %0, {%1, %2};" : "=l"(r) : "f"(a), "f"(b));
    return r;
}
__device__ __forceinline__ void cpa16(uint32_t dst, const void* src) {
    asm volatile("cp.async.cg.shared.global [%0], [%1], 16;" :: "r"(dst), "l"(src));
}
#define CP_COMMIT() asm volatile("cp.async.commit_group;")
#define CP_WAIT1()  asm volatile("cp.async.wait_group 1;")
__device__ __forceinline__ uint32_t s2u(const void* p) {
    return (uint32_t)__cvta_generic_to_shared(p);
}
__device__ __forceinline__ void ldsm4(uint32_t& r0, uint32_t& r1,
                                      uint32_t& r2, uint32_t& r3,
                                      const __half* addr) {
    asm volatile("ldmatrix.sync.aligned.m8n8.x4.shared.b16 {%0,%1,%2,%3}, [%4];"
        : "=r"(r0), "=r"(r1), "=r"(r2), "=r"(r3) : "r"(s2u(addr)));
}

// ============================================================================
// kernel 0: x transpose -> fp16 [b][n][c]; first blocks also convert weights
// ============================================================================
__global__ __launch_bounds__(256) void xpose(const float* __restrict__ x,
    const float* __restrict__ Wg, const float* __restrict__ Wt,
    const float* __restrict__ Wp, const float* __restrict__ Wz)
{
    __shared__ float t[64][33];
    int b  = blockIdx.z;
    int c0 = blockIdx.y * 64;
    int n0 = blockIdx.x * 32;
    const float* X = x + ((size_t)b * CINn + c0) * Nn;
    int tid = threadIdx.x;
    int tn = tid & 31, tc = tid >> 5;

    #pragma unroll
    for (int cc = tc; cc < 64; cc += 8)
        t[cc][tn] = X[(size_t)cc * Nn + n0 + tn];
    __syncthreads();

    int lane = tid & 31, warp = tid >> 5;
    __half* out = d_x16 + ((size_t)b * Nn + n0) * CINn + c0;
    #pragma unroll
    for (int nn = warp; nn < 32; nn += 8) {
        float v0 = t[2 * lane][nn], v1 = t[2 * lane + 1][nn];
        *(__half2*)&out[(size_t)nn * CINn + 2 * lane] = __floats2half2_rn(v0, v1);
    }

    // weight conversion folded in: first 128 blocks (by linear id)
    int lb = (blockIdx.z * gridDim.y + blockIdx.y) * gridDim.x + blockIdx.x;
    if (lb < 128) {
        const float* srcs[4] = {Wg, Wt, Wp, Wz};
        for (int i = lb * 256 + tid; i < 4 * 8192; i += 128 * 256) {
            int w = i >> 13;
            int e = i & 8191;
            float4 v = ((const float4*)srcs[w])[e];
            *(__half2*)&d_w16[(size_t)w * 32768 + e * 4]     = __floats2half2_rn(v.x, v.y);
            *(__half2*)&d_w16[(size_t)w * 32768 + e * 4 + 2] = __floats2half2_rn(v.z, v.w);
        }
    }
}

// ============================================================================
// kernel 1: the three 1x1-conv GEMMs on fp16 mma, K=256 fully resident
//   theta output pre-scaled by log2(e) for exp2-domain softmax.
// ============================================================================
#define PW_PITCH 264
#define PROJ_SMEM ((128 + 64) * PW_PITCH * 2)

__global__ __launch_bounds__(256) void proj_mma(
    const float* __restrict__ bg, const float* __restrict__ bt,
    const float* __restrict__ bp)
{
    extern __shared__ char psm[];
    __half* Ws = (__half*)psm;                        // [128][264]
    __half* Xs = (__half*)(psm + 128 * PW_PITCH * 2); // [64][264]

    int pb   = blockIdx.y;
    int proj = pb % 3;
    int b    = pb / 3;
    const __half* Wm = d_w16 + (size_t)proj * 32768;
    const float* bias = (proj == 0) ? bg : (proj == 1 ? bt : bp);

    const __half* X16 = d_x16 + (size_t)b * Nn * CINn;
    int n0 = blockIdx.x * 64;

    int tid = threadIdx.x;
    int lane = tid & 31, warp = tid >> 5;
    int r = lane >> 2, cl = lane & 3;
    int qrow = warp * 16 + r;

    #pragma unroll
    for (int e = tid; e < 128 * 32; e += 256) {
        int m = e >> 5, c8 = (e & 31) * 8;
        *(uint4*)&Ws[m * PW_PITCH + c8] = *(const uint4*)&Wm[(size_t)m * 256 + c8];
    }
    #pragma unroll
    for (int e = tid; e < 64 * 32; e += 256) {
        int n = e >> 5, c8 = (e & 31) * 8;
        *(uint4*)&Xs[n * PW_PITCH + c8] =
            *(const uint4*)&X16[(size_t)(n0 + n) * CINn + c8];
    }
    __syncthreads();

    float acc[8][4];
    #pragma unroll
    for (int i = 0; i < 8; i++)
        #pragma unroll
        for (int j = 0; j < 4; j++) acc[i][j] = 0.f;

    #pragma unroll
    for (int kk = 0; kk < CINn; kk += 16) {
        uint32_t a0 = ldu32(&Ws[qrow       * PW_PITCH + kk + 2 * cl    ]);
        uint32_t a1 = ldu32(&Ws[(qrow + 8) * PW_PITCH + kk + 2 * cl    ]);
        uint32_t a2 = ldu32(&Ws[qrow       * PW_PITCH + kk + 2 * cl + 8]);
        uint32_t a3 = ldu32(&Ws[(qrow + 8) * PW_PITCH + kk + 2 * cl + 8]);
        #pragma unroll
        for (int nt = 0; nt < 8; nt++) {
            int nc = nt * 8 + r;
            uint32_t b0 = ldu32(&Xs[nc * PW_PITCH + kk + 2 * cl    ]);
            uint32_t b1 = ldu32(&Xs[nc * PW_PITCH + kk + 2 * cl + 8]);
            mma16(acc[nt], a0, a1, a2, a3, b0, b1);
        }
    }

    float bi0 = bias[qrow], bi1 = bias[qrow + 8];
    if (proj == 0) {
        __half* out = d_g16 + (size_t)b * Fn * Nn;
        #pragma unroll
        for (int nt = 0; nt < 8; nt++) {
            int nc = n0 + nt * 8 + 2 * cl;
            *(__half2*)&out[(size_t)qrow * Nn + nc] =
                __floats2half2_rn(acc[nt][0] + bi0, acc[nt][1] + bi0);
            *(__half2*)&out[(size_t)(qrow + 8) * Nn + nc] =
                __floats2half2_rn(acc[nt][2] + bi1, acc[nt][3] + bi1);
        }
    } else {
        __half* out = (proj == 1 ? d_t16 : d_p16) + (size_t)b * Nn * Fn;
        float sc = (proj == 1) ? LOG2E : 1.0f;
        #pragma unroll
        for (int nt = 0; nt < 8; nt++) {
            int nc = n0 + nt * 8 + 2 * cl;
            out[(size_t)nc       * Fn + qrow    ] = __float2half_rn((acc[nt][0] + bi0) * sc);
            out[(size_t)(nc + 1) * Fn + qrow    ] = __float2half_rn((acc[nt][1] + bi0) * sc);
            out[(size_t)nc       * Fn + qrow + 8] = __float2half_rn((acc[nt][2] + bi1) * sc);
            out[(size_t)(nc + 1) * Fn + qrow + 8] = __float2half_rn((acc[nt][3] + bi1) * sc);
        }
    }
}

// ============================================================================
// kernel 2: fused flash attention, fp16 mma, 128-key stages, 3-stage cp.async,
//   theta + P in registers, ldmatrix.x4 B frags, one barrier per 128 keys.
//   Softmax: fully fp16x2 (hmax2 tree, packed shfl, hsub2+ex2.f16x2);
//   row sums via ones-fragment mma; f32x2 packed rescale/normalize.
// ============================================================================
#define PH_HALVES (128 * 136)          // phi stage  [m][f],   m-chunk 128
#define GS_HALVES (128 * 136)          // g   stage  [f][m],   m-chunk 128
#define STAGE_HALVES (PH_HALVES + GS_HALVES)
#define ATTN_SMEM (3 * STAGE_HALVES * 2)

__global__ __launch_bounds__(256, 1) void attn_kernel()
{
    extern __shared__ __half sh[];

    int b  = blockIdx.y;
    int q0 = blockIdx.x * 128;
    const __half* t16 = d_t16 + (size_t)b * Nn * Fn;
    const __half* p16 = d_p16 + (size_t)b * Nn * Fn;
    const __half* g16 = d_g16 + (size_t)b * Fn * Nn;

    int tid  = threadIdx.x;
    int lane = tid & 31, warp = tid >> 5;
    int r = lane >> 2, cl = lane & 3;
    int qrow = warp * 16 + r;
    int lg = lane >> 3;
    int li = lane & 7;
    int rlo = (lg >> 1) * 8 + li;
    int koff = (lg & 1) * 8;

    // ---- theta fragments -> registers (one-time gmem read, pre-scaled) ----
    uint32_t th[8][4];
    {
        const __half* t0 = &t16[(size_t)(q0 + qrow) * Fn];
        const __half* t1 = &t16[(size_t)(q0 + qrow + 8) * Fn];
        #pragma unroll
        for (int kk = 0; kk < 8; kk++) {
            th[kk][0] = ldu32(&t0[kk * 16 + 2 * cl]);
            th[kk][1] = ldu32(&t1[kk * 16 + 2 * cl]);
            th[kk][2] = ldu32(&t0[kk * 16 + 2 * cl + 8]);
            th[kk][3] = ldu32(&t1[kk * 16 + 2 * cl + 8]);
        }
    }

    float oc[16][4];
    #pragma unroll
    for (int i = 0; i < 16; i++)
        #pragma unroll
        for (int j = 0; j < 4; j++) oc[i][j] = 0.f;

    float m0_ = -3.0e38f, m1_ = -3.0e38f;
    float l0_ = 0.f,      l1_ = 0.f;

    // ---- cp.async stage issue: 128 keys (256 threads, 16B each x16) ----
    auto issue = [&](int mb, int s) {
        __half* ph = sh + s * STAGE_HALVES;
        __half* gs = ph + PH_HALVES;
        #pragma unroll
        for (int i = 0; i < 8; i++) {
            int e = tid + i * 256;
            int m = e >> 4, c8 = (e & 15) * 8;
            cpa16(s2u(&ph[m * 136 + c8]), &p16[(size_t)(mb + m) * Fn + c8]);
        }
        #pragma unroll
        for (int i = 0; i < 8; i++) {
            int e = tid + i * 256;
            int f = e >> 4, c8 = (e & 15) * 8;
            cpa16(s2u(&gs[f * 136 + c8]), &g16[(size_t)f * Nn + mb + c8]);
        }
    };

    issue(0, 0);   CP_COMMIT();
    issue(128, 1); CP_COMMIT();

    const int NCH = Nn / 128;            // 32 stages
    for (int ic = 0; ic < NCH; ic++) {
        CP_WAIT1();
        __syncthreads();
        if (ic + 2 < NCH) issue((ic + 2) * 128, (ic + 2) % 3);
        CP_COMMIT();

        const __half* ph = sh + (ic % 3) * STAGE_HALVES;
        const __half* gs = ph + PH_HALVES;

        #pragma unroll
        for (int mh = 0; mh < 2; mh++) {      // two 64-key halves per stage
            const __half* phh = ph + mh * 64 * 136;
            int goff = mh * 64;

            // ---- S = theta phi^T : 16q x 64m ----
            float sc[8][4];
            #pragma unroll
            for (int i = 0; i < 8; i++)
                #pragma unroll
                for (int j = 0; j < 4; j++) sc[i][j] = 0.f;

            #pragma unroll
            for (int kk = 0; kk < 8; kk++) {
                uint32_t bf[16];
                #pragma unroll
                for (int p2 = 0; p2 < 4; p2++) {
                    ldsm4(bf[p2 * 4 + 0], bf[p2 * 4 + 1], bf[p2 * 4 + 2], bf[p2 * 4 + 3],
                          &phh[(p2 * 16 + rlo) * 136 + kk * 16 + koff]);
                }
                #pragma unroll
                for (int nt = 0; nt < 8; nt++) {
                    mma16(sc[nt], th[kk][0], th[kk][1], th[kk][2], th[kk][3],
                          bf[nt * 2], bf[nt * 2 + 1]);
                }
            }

            // ---- softmax, fully fp16x2 ----
            // pack scores: u0[nt] = (row qrow cols), u1[nt] = (row qrow+8 cols)
            uint32_t u0[8], u1[8];
            #pragma unroll
            for (int nt = 0; nt < 8; nt++) {
                u0[nt] = packh2(sc[nt][0], sc[nt][1]);
                u1[nt] = packh2(sc[nt][2], sc[nt][3]);
            }
            // max tree in fp16x2
            uint32_t hm0 = u0[0], hm1 = u1[0];
            #pragma unroll
            for (int nt = 1; nt < 8; nt++) { hm0 = h2max(hm0, u0[nt]); hm1 = h2max(hm1, u1[nt]); }
            // combine rows into one packed value: lo = row0 max, hi = row1 max
            uint32_t hc;
            {
                uint32_t s0 = (hm0 >> 16) | (hm0 << 16);
                uint32_t s1 = (hm1 >> 16) | (hm1 << 16);
                hm0 = h2max(hm0, s0);             // both halves = row0 max
                hm1 = h2max(hm1, s1);             // both halves = row1 max
                asm("prmt.b32 %0, %1, %2, 0x7610;" : "=r"(hc) : "r"(hm0), "r"(hm1));
            }
            // cross-lane (4-lane column group) on the single packed stream
            #pragma unroll
            for (int o = 1; o < 4; o <<= 1)
                hc = h2max(hc, __shfl_xor_sync(0xffffffffu, hc, o));
            __half2 hcv = *(__half2*)&hc;
            float mx0 = __low2float(hcv), mx1 = __high2float(hcv);

            float nm0 = fmaxf(m0_, mx0), nm1 = fmaxf(m1_, mx1);
            float al0 = exp2f(m0_ - nm0), al1 = exp2f(m1_ - nm1);
            m0_ = nm0; m1_ = nm1;

            uint32_t nm00 = packh2(nm0, nm0), nm11 = packh2(nm1, nm1);
            uint32_t pp[8], pq[8];
            #pragma unroll
            for (int nt = 0; nt < 8; nt++) {
                pp[nt] = h2exp2(h2sub(u0[nt], nm00));
                pq[nt] = h2exp2(h2sub(u1[nt], nm11));
            }

            // packed f32x2 rescale of accumulators
            unsigned long long al00 = packf2(al0, al0), al11 = packf2(al1, al1);
            #pragma unroll
            for (int ft = 0; ft < 16; ft++) {
                mulx2(&oc[ft][0], al00);
                mulx2(&oc[ft][2], al11);
            }

            // ---- O += P G^T ; row sums via ones-fragment mma ----
            float lc[4] = {0.f, 0.f, 0.f, 0.f};
            #pragma unroll
            for (int j = 0; j < 4; j++) {
                uint32_t a0 = pp[2 * j], a1 = pq[2 * j];
                uint32_t a2 = pp[2 * j + 1], a3 = pq[2 * j + 1];
                mma16(lc, a0, a1, a2, a3, ONES_H2, ONES_H2);
                uint32_t gf[32];
                #pragma unroll
                for (int p2 = 0; p2 < 8; p2++) {
                    ldsm4(gf[p2 * 4 + 0], gf[p2 * 4 + 1], gf[p2 * 4 + 2], gf[p2 * 4 + 3],
                          &gs[(p2 * 16 + rlo) * 136 + goff + j * 16 + koff]);
                }
                #pragma unroll
                for (int ft = 0; ft < 16; ft++) {
                    mma16(oc[ft], a0, a1, a2, a3, gf[ft * 2], gf[ft * 2 + 1]);
                }
            }
            l0_ = l0_ * al0 + lc[0];
            l1_ = l1_ * al1 + lc[2];
        }
    }

    // ---- epilogue: normalize (f32x2), write y [n][f] fp16 from registers ----
    float li0 = 1.0f / l0_, li1 = 1.0f / l1_;
    unsigned long long li00 = packf2(li0, li0), li11 = packf2(li1, li1);
    __half* yb = d_y16 + ((size_t)b * Nn + q0) * Fn;
    #pragma unroll
    for (int ft = 0; ft < 16; ft++) {
        mulx2(&oc[ft][0], li00);
        mulx2(&oc[ft][2], li11);
        int fb = ft * 8 + 2 * cl;
        *(__half2*)&yb[(size_t)qrow * Fn + fb] =
            __floats2half2_rn(oc[ft][0], oc[ft][1]);
        *(__half2*)&yb[(size_t)(qrow + 8) * Fn + fb] =
            __floats2half2_rn(oc[ft][2], oc[ft][3]);
    }
}

// ============================================================================
// kernel 3: z = Wz @ y + bz on fp16 mma (single K pass), LN partials fused
// ============================================================================
#define ZW_PITCH 136
#define ZY_PITCH 136
#define ZG_SMEM (128 * ZW_PITCH * 2 + 64 * ZY_PITCH * 2)

__global__ __launch_bounds__(256) void zgemm_mma(const float* __restrict__ bz)
{
    extern __shared__ char zsm[];
    __half* Ws = (__half*)zsm;                        // [128][136]
    __half* Ys = (__half*)(zsm + 128 * ZW_PITCH * 2); // [64][136]

    int b  = blockIdx.z;
    int m0 = blockIdx.y * 128;
    int n0 = blockIdx.x * 64;
    const __half* W16z = d_w16 + (size_t)3 * 32768;   // [256][128]
    const __half* Y16 = d_y16 + (size_t)b * Nn * Fn;
    float* Z = d_z + (size_t)b * CINn * Nn;

    int tid = threadIdx.x;
    int lane = tid & 31, warp = tid >> 5;
    int r = lane >> 2, cl = lane & 3;
    int qrow = warp * 16 + r;

    #pragma unroll
    for (int e = tid; e < 128 * 16; e += 256) {
        int m = e >> 4, c8 = (e & 15) * 8;
        *(uint4*)&Ws[m * ZW_PITCH + c8] =
            *(const uint4*)&W16z[(size_t)(m0 + m) * Fn + c8];
    }
    #pragma unroll
    for (int e = tid; e < 64 * 16; e += 256) {
        int n = e >> 4, c8 = (e & 15) * 8;
        *(uint4*)&Ys[n * ZY_PITCH + c8] = *(const uint4*)&Y16[(size_t)(n0 + n) * Fn + c8];
    }
    __syncthreads();

    float acc[8][4];
    #pragma unroll
    for (int i = 0; i < 8; i++)
        #pragma unroll
        for (int j = 0; j < 4; j++) acc[i][j] = 0.f;

    #pragma unroll
    for (int kk = 0; kk < Fn; kk += 16) {
        uint32_t a0 = ldu32(&Ws[qrow       * ZW_PITCH + kk + 2 * cl    ]);
        uint32_t a1 = ldu32(&Ws[(qrow + 8) * ZW_PITCH + kk + 2 * cl    ]);
        uint32_t a2 = ldu32(&Ws[qrow       * ZW_PITCH + kk + 2 * cl + 8]);
        uint32_t a3 = ldu32(&Ws[(qrow + 8) * ZW_PITCH + kk + 2 * cl + 8]);
        #pragma unroll
        for (int nt = 0; nt < 8; nt++) {
            int nc = nt * 8 + r;
            uint32_t b0 = ldu32(&Ys[nc * ZY_PITCH + kk + 2 * cl    ]);
            uint32_t b1 = ldu32(&Ys[nc * ZY_PITCH + kk + 2 * cl + 8]);
            mma16(acc[nt], a0, a1, a2, a3, b0, b1);
        }
    }
    __syncthreads();

    float bi0 = bz[m0 + qrow], bi1 = bz[m0 + qrow + 8];
    float lsum = 0.f, lsq = 0.f;
    #pragma unroll
    for (int nt = 0; nt < 8; nt++) {
        int nc = n0 + nt * 8 + 2 * cl;
        float v0 = acc[nt][0] + bi0, v1 = acc[nt][1] + bi0;
        float v2 = acc[nt][2] + bi1, v3 = acc[nt][3] + bi1;
        *(float2*)&Z[(size_t)(m0 + qrow) * Nn + nc]     = make_float2(v0, v1);
        *(float2*)&Z[(size_t)(m0 + qrow + 8) * Nn + nc] = make_float2(v2, v3);
        lsum += v0 + v1 + v2 + v3;
        lsq  += v0 * v0 + v1 * v1 + v2 * v2 + v3 * v3;
    }

    float* rs = (float*)zsm;
    float* rq = rs + 256;
    rs[tid] = lsum; rq[tid] = lsq;
    __syncthreads();
    #pragma unroll
    for (int s = 128; s > 0; s >>= 1) {
        if (tid < s) { rs[tid] += rs[tid + s]; rq[tid] += rq[tid + s]; }
        __syncthreads();
    }
    if (tid == 0) {
        int idx = b * 128 + blockIdx.y * 64 + blockIdx.x;
        d_part[2 * idx]     = rs[0];
        d_part[2 * idx + 1] = rq[0];
    }
}

// ---------------- kernel 4: per-batch mean / rsig ---------------------------
__global__ __launch_bounds__(128) void stats_kernel()
{
    int b = blockIdx.x;
    int tid = threadIdx.x;
    __shared__ float rs[128], rq[128];
    int idx = b * 128 + tid;
    rs[tid] = d_part[2 * idx];
    rq[tid] = d_part[2 * idx + 1];
    __syncthreads();
    #pragma unroll
    for (int s = 64; s > 0; s >>= 1) {
        if (tid < s) { rs[tid] += rs[tid + s]; rq[tid] += rq[tid + s]; }
        __syncthreads();
    }
    if (tid == 0) {
        float inv = 1.0f / ((float)CINn * (float)Nn);
        float mu  = rs[0] * inv;
        float var = rq[0] * inv - mu * mu;
        d_stats[2 * b]     = mu;
        d_stats[2 * b + 1] = rsqrtf(var + EPSc);
    }
}

// ---------------- kernel 5: LN affine + residual ----------------------------
__global__ __launch_bounds__(256) void finalize_kernel(
    const float* __restrict__ x, const float* __restrict__ lw,
    const float* __restrict__ lb, float* __restrict__ out)
{
    const int per_b4 = CINn * Nn / 4;
    const int tot4   = Bn * per_b4;
    for (int i = blockIdx.x * blockDim.x + threadIdx.x; i < tot4;
         i += gridDim.x * blockDim.x) {
        int b = i / per_b4;
        int r = i - b * per_b4;
        float mu   = d_stats[2 * b];
        float rsig = d_stats[2 * b + 1];
        float4 z  = ((const float4*)d_z)[i];
        float4 xv = ((const float4*)x)[i];
        float4 w  = ((const float4*)lw)[r];
        float4 bb = ((const float4*)lb)[r];
        float4 o;
        o.x = (z.x - mu) * rsig * w.x + bb.x + xv.x;
        o.y = (z.y - mu) * rsig * w.y + bb.y + xv.y;
        o.z = (z.z - mu) * rsig * w.z + bb.z + xv.z;
        o.w = (z.w - mu) * rsig * w.w + bb.w + xv.w;
        ((float4*)out)[i] = o;
    }
}

// ---------------- launch -----------------------------------------------------
extern "C" void kernel_launch(void* const* d_in, const int* in_sizes, int n_in,
                              void* d_out, int out_size)
{
    const float* x   = (const float*)d_in[0];
    const float* Wg  = (const float*)d_in[1];
    const float* bg  = (const float*)d_in[2];
    const float* Wt  = (const float*)d_in[3];
    const float* bt  = (const float*)d_in[4];
    const float* Wp  = (const float*)d_in[5];
    const float* bp  = (const float*)d_in[6];
    const float* Wz  = (const float*)d_in[7];
    const float* bz  = (const float*)d_in[8];
    const float* lnw = (const float*)d_in[9];
    const float* lnb = (const float*)d_in[10];
    float* out = (float*)d_out;

    cudaFuncSetAttribute(attn_kernel, cudaFuncAttributeMaxDynamicSharedMemorySize,
                         ATTN_SMEM);
    cudaFuncSetAttribute(proj_mma, cudaFuncAttributeMaxDynamicSharedMemorySize,
                         PROJ_SMEM);
    cudaFuncSetAttribute(zgemm_mma, cudaFuncAttributeMaxDynamicSharedMemorySize,
                         ZG_SMEM);

    xpose<<<dim3(128, 4, 4), 256>>>(x, Wg, Wt, Wp, Wz);
    proj_mma<<<dim3(64, 12), 256, PROJ_SMEM>>>(bg, bt, bp);
    attn_kernel<<<dim3(32, 4), 256, ATTN_SMEM>>>();
    zgemm_mma<<<dim3(64, 2, 4), 256, ZG_SMEM>>>(bz);
    stats_kernel<<<4, 128>>>();
    finalize_kernel<<<4096, 256>>>(x, lnw, lnb, out);
}